// round 14
// baseline (speedup 1.0000x reference)
#include <cuda_runtime.h>
#include <cuda_fp16.h>
#include <cstdint>

// ---------------------------------------------------------------------------
// Sparse submanifold 3D conv backbone, batch=1, 128^3 -> 2^3.
// L0 conv1 (Cin=3): neighbor-skipping scalar, writes fp16 feature table.
// L0c2..L3: mma.sync pure fp16 (fp32 accum), K=128 per pipeline stage
// (2 x 64-chunk sub-buffers per stage; zero-filled tail chunk if odd).
// Levels 4-6 (n <= 512): scalar FFMA path.
// ---------------------------------------------------------------------------

#define NMAX 100000
#define GRID_CELLS (1 << 21)
#define FLAGS_MAX (1 << 18)

__device__ int   g_n[8];
__device__ int   g_linA[NMAX];
__device__ int   g_linB[NMAX];
__device__ int   g_gridA[GRID_CELLS];
__device__ int   g_gridB[GRID_CELLS];
__device__ int   g_pairs[27 * NMAX];
__device__ int   g_flags[FLAGS_MAX];
__device__ int   g_bsums[256];
__device__ __align__(1024) float g_featA[10000000];
__device__ __align__(1024) float g_featB[10000000];
// fp16 feature tables: t1 = conv1 input, t2 = conv2 input
__device__ __align__(1024) __half g_fh1[12000000];
__device__ __align__(1024) __half g_fh2[12000000];
// pre-swizzled, transposed fp16 weight blob (layers 1..7)
__device__ __align__(1024) unsigned char g_wblob[16 * 1024 * 1024];

// ---------------------------------------------------------------------------

__device__ __forceinline__ void cp_async16(uint32_t dst, const void* src, int srcBytes) {
    asm volatile("cp.async.cg.shared.global [%0], [%1], 16, %2;\n"
                 :: "r"(dst), "l"(src), "r"(srcBytes));
}
__device__ __forceinline__ void cp_commit() {
    asm volatile("cp.async.commit_group;\n");
}
__device__ __forceinline__ uint32_t smem_u32(const void* p) {
    uint32_t a;
    asm("{ .reg .u64 t; cvta.to.shared.u64 t, %1; cvt.u32.u64 %0, t; }" : "=r"(a) : "l"(p));
    return a;
}
__device__ __forceinline__ void ldsm4(uint32_t* r, uint32_t addr) {
    asm volatile("ldmatrix.sync.aligned.m8n8.x4.shared.b16 {%0,%1,%2,%3}, [%4];"
                 : "=r"(r[0]), "=r"(r[1]), "=r"(r[2]), "=r"(r[3]) : "r"(addr));
}
__device__ __forceinline__ void ldsm2(uint32_t* r, uint32_t addr) {
    asm volatile("ldmatrix.sync.aligned.m8n8.x2.shared.b16 {%0,%1}, [%2];"
                 : "=r"(r[0]), "=r"(r[1]) : "r"(addr));
}
__device__ __forceinline__ void mma16816(float* d, const uint32_t* a, const uint32_t* b) {
    asm volatile("mma.sync.aligned.m16n8k16.row.col.f32.f16.f16.f32 "
                 "{%0,%1,%2,%3}, {%4,%5,%6,%7}, {%8,%9}, {%0,%1,%2,%3};"
                 : "+f"(d[0]), "+f"(d[1]), "+f"(d[2]), "+f"(d[3])
                 : "r"(a[0]), "r"(a[1]), "r"(a[2]), "r"(a[3]), "r"(b[0]), "r"(b[1]));
}

// ---------------------------------------------------------------------------

__global__ void k_setn(int n0) { g_n[0] = n0; }

__global__ void k_fill(int* g, int v, int P) {
    int i = blockIdx.x * blockDim.x + threadIdx.x;
    if (i < P) g[i] = v;
}

__global__ void k_scatter0(const int* __restrict__ coors, int n0) {
    int i = blockIdx.x * blockDim.x + threadIdx.x;
    if (i >= n0) return;
    int z = coors[i * 4 + 1];
    int y = coors[i * 4 + 2];
    int x = coors[i * 4 + 3];
    int l = (z * 128 + y) * 128 + x;
    g_linA[i] = l;
    g_gridA[l] = i;
}

__global__ void k_pairs(const int* __restrict__ lin, const int* __restrict__ grid,
                        const int* __restrict__ np, int S) {
    int n = *np;
    int i = blockIdx.x * blockDim.x + threadIdx.x;
    if (i >= n) return;
    int l = lin[i];
    int z = l / (S * S);
    int rem = l - z * S * S;
    int y = rem / S;
    int x = rem - y * S;
    int k = 0;
    #pragma unroll
    for (int dz = -1; dz <= 1; dz++)
        #pragma unroll
        for (int dy = -1; dy <= 1; dy++)
            #pragma unroll
            for (int dx = -1; dx <= 1; dx++) {
                int zz = z + dz, yy = y + dy, xx = x + dx;
                int v = -1;
                if (zz >= 0 && zz < S && yy >= 0 && yy < S && xx >= 0 && xx < S)
                    v = grid[(zz * S + yy) * S + xx];
                g_pairs[k * NMAX + i] = v;
                k++;
            }
}

// Weight blob: W[27,Cin,Cout] fp32 -> per-chunk SW128 images of W^T
// [Cout rows x 64 cols] fp16 single-limb. Chunk = (k, ci-chunk).
__global__ void k_wcvt(const float* __restrict__ W, unsigned char* __restrict__ blob,
                       int Cin, int CinP, int Cout) {
    int total = 27 * CinP * Cout;
    int idx = blockIdx.x * 256 + threadIdx.x;
    if (idx >= total) return;
    int ci = idx % CinP;
    int t = idx / CinP;
    int co = t % Cout;
    int k = t / Cout;
    float v = (ci < Cin) ? W[((size_t)k * Cin + ci) * Cout + co] : 0.f;
    __half h = __float2half_rn(v);
    int ch = ci >> 6, cic = ci & 63;
    int sw = (((cic >> 3) ^ (co & 7)) << 4) + (cic & 7) * 2;
    int NCH = CinP >> 6;
    size_t stageBase = (size_t)(k * NCH + ch) * (Cout * 128);
    *(__half*)(blob + stageBase + (size_t)co * 128 + sw) = h;
}

// ---------------------------------------------------------------------------
// Fused L0 conv1: Cin=3, Cout=64, writes fp16 table (CP=64), skips missing.
// ---------------------------------------------------------------------------
__global__ __launch_bounds__(256) void k_conv0(const float* __restrict__ feats,
                                               const float* __restrict__ W,
                                               __half* __restrict__ out,
                                               const int* __restrict__ np) {
    __shared__ float Ws[27 * 3 * 64];
    int n = *np;
    int tid = threadIdx.x;
    for (int e = tid; e < 27 * 3 * 64; e += 256) Ws[e] = W[e];
    __syncthreads();
    int r = blockIdx.x * 4 + (tid >> 6);
    int lane = tid & 63;
    if (r >= n) return;
    float acc = 0.f;
    #pragma unroll 1
    for (int k = 0; k < 27; k++) {
        int id = g_pairs[k * NMAX + r];
        if (id >= 0) {
            float f0 = feats[id * 3 + 0];
            float f1 = feats[id * 3 + 1];
            float f2 = feats[id * 3 + 2];
            const float* wk = Ws + k * 192;
            acc += f0 * wk[lane] + f1 * wk[64 + lane] + f2 * wk[128 + lane];
        }
    }
    out[(size_t)r * 64 + lane] = __float2half_rn(acc);
}

// ---------------------------------------------------------------------------
// mma.sync conv: 128-row tile x CoutS col slice, pure fp16, fp32 accumulate.
// 512 threads = 16 warps = 4 row-groups x 4 col-quarters.
// 2-stage cp.async pipeline with K=128 per stage (2 x 64-chunks).
// ---------------------------------------------------------------------------
template <int NT>   // NT = CoutS/8, divisible by 4 (or 4)
__global__ __launch_bounds__(512) void k_wconv(
    const __half* __restrict__ fin,
    const unsigned char* __restrict__ wblob,
    float* __restrict__ outF,
    __half* __restrict__ outH, int CP,
    const int* __restrict__ np, int CinP, int CoutF)
{
    const int NT4 = NT / 4;
    const int CoutS = NT * 8;
    const int WchunkS = CoutS * 128;      // one chunk's W image
    const int WstageS = 2 * WchunkS;      // per pipeline stage
    int n = *np;
    int rowBase = blockIdx.x * 128;
    if (rowBase >= n) return;
    int colBase = blockIdx.y * CoutS;

    extern __shared__ __align__(1024) unsigned char sm[];
    const uint32_t Asm = smem_u32(sm);        // 2 stages x 32KB (2 chunks each)
    const uint32_t Wsm = Asm + 2 * 32768;

    int tid = threadIdx.x;
    int wid = tid >> 5;
    int lane = tid & 31;

    const int NCH = CinP >> 6;
    const int Ctot = 27 * NCH;            // total 64-wide K chunks
    const int S = (Ctot + 1) >> 1;        // pipeline stages (K=128 each)
    const int WchunkF = CoutF * 128;

    // A-gather: 4 threads per row: cidx (chunk of stage) x ahalf (64B half)
    int am = tid >> 2;        // 0..127 row
    int sub = tid & 3;
    int cidx = sub >> 1;      // which chunk within the stage (parity fixed)
    int ahalf = sub & 1;
    int r_g = rowBase + am;
    int curK = -1, curId = -1;

    float acc[2][NT4][4];
    #pragma unroll
    for (int mt = 0; mt < 2; mt++)
        #pragma unroll
        for (int j = 0; j < NT4; j++)
            #pragma unroll
            for (int p = 0; p < 4; p++) acc[mt][j][p] = 0.f;

    auto load = [&](int buf, int s) {
        // ---- A: this thread's chunk g = 2s + cidx ----
        {
            int g = 2 * s + cidx;
            int valid = (g < Ctot);
            int id = -1;
            if (valid) {
                int k = g / NCH;
                if (k != curK) {
                    curK = k;
                    curId = (r_g < n) ? g_pairs[k * NMAX + r_g] : -1;
                }
                id = curId;
            }
            int ch = valid ? (2 * s + cidx) - curK * NCH : 0;
            const unsigned char* src =
                (const unsigned char*)(fin + (size_t)(id < 0 ? 0 : id) * CinP + ch * 64);
            uint32_t dst = Asm + buf * 32768 + cidx * 16384 + am * 128;
            int m7 = (am & 7) << 4;
            int sz = (valid && id >= 0) ? 16 : 0;
            #pragma unroll
            for (int j = 0; j < 4; j++) {
                int c = ahalf * 4 + j;
                cp_async16(dst + ((c << 4) ^ m7), src + c * 16, sz);
            }
        }
        // ---- W: two chunk images ----
        {
            const int hc = WchunkS >> 4;
            uint32_t dst = Wsm + buf * WstageS;
            for (int e = tid; e < 2 * hc; e += 512) {
                int ci = (e >= hc) ? 1 : 0;
                int e2 = e - ci * hc;
                int g = 2 * s + ci;
                int valid = (g < Ctot);
                const unsigned char* sp = valid
                    ? wblob + (size_t)g * WchunkF + (size_t)colBase * 128 + e2 * 16
                    : wblob;
                cp_async16(dst + e * 16, sp, valid ? 16 : 0);
            }
        }
        cp_commit();
    };

    int rw = wid & 3;
    int cw = wid >> 2;
    int arow0 = rw * 32 + (lane & 15);
    int ac16 = (lane >> 4) & 1;
    int brow_l = lane & 7;
    int bc16 = (lane >> 3) & 1;

    load(0, 0);
    for (int s = 0; s < S; s++) {
        int b = s & 1;
        if (s + 1 < S) {
            load(b ^ 1, s + 1);
            asm volatile("cp.async.wait_group 1;\n");
        } else {
            asm volatile("cp.async.wait_group 0;\n");
        }
        __syncthreads();

        #pragma unroll
        for (int cp = 0; cp < 2; cp++) {
            uint32_t AB = Asm + b * 32768 + cp * 16384;
            uint32_t WB = Wsm + b * WstageS + cp * WchunkS;
            #pragma unroll
            for (int chunk = 0; chunk < 4; chunk++) {
                uint32_t ah[2][4];
                #pragma unroll
                for (int mt = 0; mt < 2; mt++) {
                    uint32_t off = (uint32_t)(arow0 + mt * 16) * 128 + chunk * 32 + ac16 * 16;
                    off ^= (off >> 3) & 0x70;
                    ldsm4(ah[mt], AB + off);
                }
                #pragma unroll
                for (int j = 0; j < NT4; j++) {
                    uint32_t off = (uint32_t)(cw * (NT4 * 8) + j * 8 + brow_l) * 128
                                 + chunk * 32 + bc16 * 16;
                    off ^= (off >> 3) & 0x70;
                    uint32_t bh[2];
                    ldsm2(bh, WB + off);
                    #pragma unroll
                    for (int mt = 0; mt < 2; mt++)
                        mma16816(acc[mt][j], ah[mt], bh);
                }
            }
        }
        __syncthreads();
    }

    int grp = lane >> 2, tg = lane & 3;
    #pragma unroll
    for (int mt = 0; mt < 2; mt++) {
        int r0 = rowBase + rw * 32 + mt * 16 + grp;
        #pragma unroll
        for (int half = 0; half < 2; half++) {
            int r = r0 + half * 8;
            if (r >= n) continue;
            #pragma unroll
            for (int j = 0; j < NT4; j++) {
                float d0 = acc[mt][j][half * 2 + 0];
                float d1 = acc[mt][j][half * 2 + 1];
                int c = colBase + cw * (NT4 * 8) + j * 8 + tg * 2;
                if (outF) {
                    float2 v; v.x = d0; v.y = d1;
                    *(float2*)(outF + (size_t)r * CoutF + c) = v;
                }
                if (outH) {
                    __half h0 = __float2half_rn(d0);
                    __half h1 = __float2half_rn(d1);
                    uint32_t hp = ((uint32_t)(*(unsigned short*)&h1) << 16)
                                | (uint32_t)(*(unsigned short*)&h0);
                    *(uint32_t*)(outH + (size_t)r * CP + c) = hp;
                }
            }
            if (outH && blockIdx.y == 0 && cw == 0) {
                for (int c = CoutF + tg * 2; c < CP; c += 8)
                    *(uint32_t*)(outH + (size_t)r * CP + c) = 0u;
            }
        }
    }
}

// ---------------------------------------------------------------------------
// Small-level scalar conv (n <= 512): 16 rows x 32 cols per block.
// ---------------------------------------------------------------------------
__global__ __launch_bounds__(256) void k_conv_small(const float* __restrict__ feats,
                                                    const float* __restrict__ W,
                                                    float* __restrict__ out,
                                                    const int* __restrict__ np,
                                                    int Cin, int Cout) {
    int n = *np;
    int rowBase = blockIdx.x * 16;
    if (rowBase >= n) return;
    int colBase = blockIdx.y * 32;

    __shared__ float As[16][33];
    __shared__ float Ws[32][33];

    int tid = threadIdx.x;
    int tm = tid >> 5;
    int tn = tid & 31;

    float acc0 = 0.f, acc1 = 0.f;

    for (int k = 0; k < 27; k++) {
        for (int c0 = 0; c0 < Cin; c0 += 32) {
            __syncthreads();
            {
                int e = tid;
                #pragma unroll
                for (int j = 0; j < 2; j++, e += 256) {
                    int m = e >> 5, c = e & 31;
                    int r = rowBase + m;
                    int id = (r < n) ? g_pairs[k * NMAX + r] : -1;
                    As[m][c] = (id >= 0) ? feats[(size_t)id * Cin + c0 + c] : 0.f;
                }
            }
            {
                const float* Wk = W + ((size_t)k * Cin + c0) * Cout + colBase;
                int e = tid;
                #pragma unroll
                for (int j = 0; j < 4; j++, e += 256) {
                    int kk = e >> 5, c = e & 31;
                    Ws[kk][c] = Wk[(size_t)kk * Cout + c];
                }
            }
            __syncthreads();
            #pragma unroll 8
            for (int kk = 0; kk < 32; kk++) {
                float w = Ws[kk][tn];
                acc0 += As[tm * 2][kk] * w;
                acc1 += As[tm * 2 + 1][kk] * w;
            }
        }
    }

    int r0 = rowBase + tm * 2;
    if (r0 < n)     out[(size_t)r0 * Cout + colBase + tn] = acc0;
    if (r0 + 1 < n) out[(size_t)(r0 + 1) * Cout + colBase + tn] = acc1;
}

// ---------------------------------------------------------------------------
// Pool structure kernels + pool with optional fp16 output table
// ---------------------------------------------------------------------------
__global__ void k_flags(const int* __restrict__ fineGrid, int S) {
    int Sc = S >> 1;
    int P = Sc * Sc * Sc;
    int p = blockIdx.x * blockDim.x + threadIdx.x;
    if (p >= P) return;
    int pz = p / (Sc * Sc);
    int rem = p - pz * Sc * Sc;
    int py = rem / Sc;
    int px = rem - py * Sc;
    int occ = 0;
    #pragma unroll
    for (int a = 0; a < 2; a++)
        #pragma unroll
        for (int b = 0; b < 2; b++)
            #pragma unroll
            for (int c = 0; c < 2; c++) {
                int l = ((2 * pz + a) * S + 2 * py + b) * S + 2 * px + c;
                if (fineGrid[l] >= 0) occ = 1;
            }
    g_flags[p] = occ;
}

__global__ void k_scanA(int P) {
    __shared__ int sh[256];
    int t = threadIdx.x;
    int base = blockIdx.x * 1024;
    int s = 0;
    #pragma unroll
    for (int j = 0; j < 4; j++) {
        int p = base + t * 4 + j;
        if (p < P) s += g_flags[p];
    }
    sh[t] = s;
    __syncthreads();
    for (int d = 128; d > 0; d >>= 1) {
        if (t < d) sh[t] += sh[t + d];
        __syncthreads();
    }
    if (t == 0) g_bsums[blockIdx.x] = sh[0];
}

__global__ void k_scanB(int nb, int Lnext) {
    __shared__ int sh[256];
    int t = threadIdx.x;
    int v = (t < nb) ? g_bsums[t] : 0;
    sh[t] = v;
    __syncthreads();
    for (int d = 1; d < 256; d <<= 1) {
        int x = (t >= d) ? sh[t - d] : 0;
        __syncthreads();
        sh[t] += x;
        __syncthreads();
    }
    if (t < nb) g_bsums[t] = sh[t] - v;
    if (t == 255) g_n[Lnext] = sh[255];
}

__global__ void k_scanC(int* __restrict__ coarseGrid, int* __restrict__ linNext, int P) {
    __shared__ int sh[256];
    int t = threadIdx.x;
    int base = blockIdx.x * 1024;
    int f[4];
    int s = 0;
    #pragma unroll
    for (int j = 0; j < 4; j++) {
        int p = base + t * 4 + j;
        f[j] = (p < P) ? g_flags[p] : 0;
        s += f[j];
    }
    int v = s;
    sh[t] = v;
    __syncthreads();
    for (int d = 1; d < 256; d <<= 1) {
        int x = (t >= d) ? sh[t - d] : 0;
        __syncthreads();
        sh[t] += x;
        __syncthreads();
    }
    int off = g_bsums[blockIdx.x] + sh[t] - v;
    #pragma unroll
    for (int j = 0; j < 4; j++) {
        int p = base + t * 4 + j;
        if (p >= P) break;
        if (f[j]) {
            coarseGrid[p] = off;
            linNext[off] = p;
            off++;
        } else {
            coarseGrid[p] = -1;
        }
    }
}

__global__ void k_pool2(const float* __restrict__ feats, float* __restrict__ out,
                        __half* __restrict__ oh,
                        const int* __restrict__ fineGrid, const int* __restrict__ linNext,
                        const int* __restrict__ np, int S, int C, int CP) {
    int row = blockIdx.x;
    if (row >= *np) return;
    int Sc = S >> 1;
    int p = linNext[row];
    int pz = p / (Sc * Sc);
    int rem = p - pz * Sc * Sc;
    int py = rem / Sc;
    int px = rem - py * Sc;
    int c = threadIdx.x;
    if (c < C) {
        float m = -3.4e38f;
        #pragma unroll
        for (int a = 0; a < 2; a++)
            #pragma unroll
            for (int b = 0; b < 2; b++)
                #pragma unroll
                for (int d = 0; d < 2; d++) {
                    int l = ((2 * pz + a) * S + 2 * py + b) * S + 2 * px + d;
                    int r = fineGrid[l];
                    if (r >= 0) m = fmaxf(m, feats[(size_t)r * C + c]);
                }
        out[(size_t)row * C + c] = m;
        if (CP) oh[(size_t)row * CP + c] = __float2half_rn(m);
    } else if (CP && c < CP) {
        oh[(size_t)row * CP + c] = __float2half_rn(0.f);
    }
}

// ---------------------------------------------------------------------------

static inline int ceildiv(int a, int b) { return (a + b - 1) / b; }
static inline int pad64(int c) { return (c + 63) & ~63; }

static void launch_wconv(const __half* fin, const unsigned char* wb, float* outF,
                         __half* oh, int CP, const int* np, int CinP, int Cout,
                         int nBound, int gy) {
    int CoutS = Cout / gy;
    int NT = CoutS / 8;
    dim3 g(ceildiv(nBound, 128), gy), b(512);
    int smem = 2 * 32768 + 2 * 2 * CoutS * 128;
    switch (NT) {
        case 4:
            cudaFuncSetAttribute(k_wconv<4>, cudaFuncAttributeMaxDynamicSharedMemorySize, smem);
            k_wconv<4><<<g, b, smem>>>(fin, wb, outF, oh, CP, np, CinP, Cout);
            break;
        case 8:
            cudaFuncSetAttribute(k_wconv<8>, cudaFuncAttributeMaxDynamicSharedMemorySize, smem);
            k_wconv<8><<<g, b, smem>>>(fin, wb, outF, oh, CP, np, CinP, Cout);
            break;
        case 12:
            cudaFuncSetAttribute(k_wconv<12>, cudaFuncAttributeMaxDynamicSharedMemorySize, smem);
            k_wconv<12><<<g, b, smem>>>(fin, wb, outF, oh, CP, np, CinP, Cout);
            break;
        case 16:
            cudaFuncSetAttribute(k_wconv<16>, cudaFuncAttributeMaxDynamicSharedMemorySize, smem);
            k_wconv<16><<<g, b, smem>>>(fin, wb, outF, oh, CP, np, CinP, Cout);
            break;
    }
}

extern "C" void kernel_launch(void* const* d_in, const int* in_sizes, int n_in,
                              void* d_out, int out_size) {
    const float* feat_in = (const float*)d_in[0];
    const int*   coors   = (const int*)d_in[1];
    const float* w[14];
    for (int i = 0; i < 14; i++) w[i] = (const float*)d_in[3 + i];

    int n0 = in_sizes[0] / 3;

    float *fA, *fB;
    __half *t1, *t2;
    unsigned char* wblob;
    int *gA, *gB, *lA, *lB, *pn;
    cudaGetSymbolAddress((void**)&fA, g_featA);
    cudaGetSymbolAddress((void**)&fB, g_featB);
    cudaGetSymbolAddress((void**)&t1, g_fh1);
    cudaGetSymbolAddress((void**)&t2, g_fh2);
    cudaGetSymbolAddress((void**)&wblob, g_wblob);
    cudaGetSymbolAddress((void**)&gA, g_gridA);
    cudaGetSymbolAddress((void**)&gB, g_gridB);
    cudaGetSymbolAddress((void**)&lA, g_linA);
    cudaGetSymbolAddress((void**)&lB, g_linB);
    cudaGetSymbolAddress((void**)&pn, g_n);

    const int S[7]  = {128, 64, 32, 16, 8, 4, 2};
    int NB[7];
    NB[0] = n0;
    NB[1] = n0 < (64 * 64 * 64) ? n0 : (64 * 64 * 64);
    NB[2] = 32 * 32 * 32;
    NB[3] = 16 * 16 * 16;
    NB[4] = 8 * 8 * 8;
    NB[5] = 4 * 4 * 4;
    NB[6] = 2 * 2 * 2;
    const int Cin1[7]  = {3, 64, 96, 128, 160, 192, 224};
    const int Cout1[7] = {64, 96, 128, 160, 192, 224, 256};

    // MMA-path layers (0..7 == L0c1..L3c2); layer 0 handled by k_conv0
    const int LCin[8]  = {3, 64, 64, 96, 96, 128, 128, 160};
    const int LCinP[8] = {64, 64, 64, 128, 128, 128, 128, 192};
    const int LCout[8] = {64, 64, 96, 96, 128, 128, 160, 160};
    size_t woff[9];
    woff[0] = 0;
    for (int i = 0; i < 8; i++)
        woff[i + 1] = woff[i] + (size_t)27 * (LCinP[i] / 64) * LCout[i] * 128;

    // ---- weight blob (layers 1..7) + level-0 structure ----
    for (int i = 1; i < 8; i++) {
        int total = 27 * LCinP[i] * LCout[i];
        k_wcvt<<<ceildiv(total, 256), 256>>>(w[i], wblob + woff[i],
                                             LCin[i], LCinP[i], LCout[i]);
    }
    k_setn<<<1, 1>>>(n0);
    k_fill<<<ceildiv(GRID_CELLS, 256), 256>>>(gA, -1, GRID_CELLS);
    k_scatter0<<<ceildiv(n0, 256), 256>>>(coors, n0);

    int* linCur = lA;
    int* gridCur = gA;
    int* linNxt = lB;
    int* gridNxt = gB;

    // ---- MMA levels 0..3 ----
    for (int L = 0; L < 4; L++) {
        const int* np = pn + L;
        k_pairs<<<ceildiv(NB[L], 256), 256>>>(linCur, gridCur, np, S[L]);

        int li1 = 2 * L, li2 = 2 * L + 1;
        int gy = (L == 3) ? 5 : 1;
        if (L == 0) {
            k_conv0<<<ceildiv(NB[0], 4), 256>>>(feat_in, w[0], t2, np);
        } else {
            launch_wconv(t1, wblob + woff[li1], nullptr, t2, LCinP[li2],
                         np, LCinP[li1], LCout[li1], NB[L], gy);
        }
        launch_wconv(t2, wblob + woff[li2], fA, nullptr, 0,
                     np, LCinP[li2], LCout[li2], NB[L], gy);

        {
            int Sc = S[L] >> 1, P = Sc * Sc * Sc, nb = ceildiv(P, 1024);
            k_flags<<<ceildiv(P, 256), 256>>>(gridCur, S[L]);
            k_scanA<<<nb, 256>>>(P);
            k_scanB<<<1, 256>>>(nb, L + 1);
            k_scanC<<<nb, 256>>>(gridNxt, linNxt, P);
            int C = LCout[li2];
            int CP = (L < 3) ? pad64(C) : 0;
            int thr = CP ? CP : C;
            k_pool2<<<NB[L + 1], thr>>>(fA, fB, t1, gridCur, linNxt,
                                        pn + L + 1, S[L], C, CP);
        }
        int* t;
        t = linCur; linCur = linNxt; linNxt = t;
        t = gridCur; gridCur = gridNxt; gridNxt = t;
    }

    // ---- FFMA levels 4..6 (pool L3 output in fB) ----
    const float* cur = fB;
    for (int L = 4; L < 7; L++) {
        const int* np = pn + L;
        k_pairs<<<ceildiv(NB[L], 256), 256>>>(linCur, gridCur, np, S[L]);
        int ci1 = Cin1[L], co1 = Cout1[L];
        float* o1 = (cur == fB) ? fA : fB;
        {
            dim3 g(ceildiv(NB[L], 16), co1 / 32), b(256);
            k_conv_small<<<g, b>>>(cur, w[2 * L], o1, np, ci1, co1);
        }
        float* o2 = (L == 6) ? (float*)d_out : ((o1 == fA) ? fB : fA);
        {
            dim3 g(ceildiv(NB[L], 16), co1 / 32), b(256);
            k_conv_small<<<g, b>>>(o1, w[2 * L + 1], o2, np, co1, co1);
        }
        cur = o2;
        if (L < 6) {
            int Sc = S[L] >> 1, P = Sc * Sc * Sc, nb = ceildiv(P, 1024);
            k_flags<<<ceildiv(P, 256), 256>>>(gridCur, S[L]);
            k_scanA<<<nb, 256>>>(P);
            k_scanB<<<1, 256>>>(nb, L + 1);
            k_scanC<<<nb, 256>>>(gridNxt, linNxt, P);
            float* po = (cur == fA) ? fB : fA;
            k_pool2<<<NB[L + 1], co1>>>(cur, po, nullptr, gridCur, linNxt,
                                        pn + L + 1, S[L], co1, 0);
            cur = po;
            int* t;
            t = linCur; linCur = linNxt; linNxt = t;
            t = gridCur; gridCur = gridNxt; gridNxt = t;
        }
    }
}

// round 15
// speedup vs baseline: 1.0248x; 1.0248x over previous
#include <cuda_runtime.h>
#include <cuda_fp16.h>
#include <cstdint>

// ---------------------------------------------------------------------------
// Sparse submanifold 3D conv backbone, batch=1, 128^3 -> 2^3.
// L0 conv1 (Cin=3): neighbor-skipping scalar, writes fp16 feature table.
// L0c2..L3: mma.sync pure fp16 (fp32 accum). CPS = K-chunks merged per
// pipeline stage (per-layer, smem-budgeted). Half-chunks (Cin%64==32) run
// only 2 of 4 K=16 sub-steps (exact skip of zero columns).
// Levels 4-6 (n <= 512): scalar FFMA path.
// ---------------------------------------------------------------------------

#define NMAX 100000
#define GRID_CELLS (1 << 21)
#define FLAGS_MAX (1 << 18)

__device__ int   g_n[8];
__device__ int   g_linA[NMAX];
__device__ int   g_linB[NMAX];
__device__ int   g_gridA[GRID_CELLS];
__device__ int   g_gridB[GRID_CELLS];
__device__ int   g_pairs[27 * NMAX];
__device__ int   g_flags[FLAGS_MAX];
__device__ int   g_bsums[256];
__device__ __align__(1024) float g_featA[10000000];
__device__ __align__(1024) float g_featB[10000000];
// fp16 feature tables: t1 = conv1 input, t2 = conv2 input
__device__ __align__(1024) __half g_fh1[12000000];
__device__ __align__(1024) __half g_fh2[12000000];
// pre-swizzled, transposed fp16 weight blob (layers 1..7)
__device__ __align__(1024) unsigned char g_wblob[16 * 1024 * 1024];

// ---------------------------------------------------------------------------

__device__ __forceinline__ void cp_async16(uint32_t dst, const void* src, int srcBytes) {
    asm volatile("cp.async.cg.shared.global [%0], [%1], 16, %2;\n"
                 :: "r"(dst), "l"(src), "r"(srcBytes));
}
__device__ __forceinline__ void cp_commit() {
    asm volatile("cp.async.commit_group;\n");
}
__device__ __forceinline__ uint32_t smem_u32(const void* p) {
    uint32_t a;
    asm("{ .reg .u64 t; cvta.to.shared.u64 t, %1; cvt.u32.u64 %0, t; }" : "=r"(a) : "l"(p));
    return a;
}
__device__ __forceinline__ void ldsm4(uint32_t* r, uint32_t addr) {
    asm volatile("ldmatrix.sync.aligned.m8n8.x4.shared.b16 {%0,%1,%2,%3}, [%4];"
                 : "=r"(r[0]), "=r"(r[1]), "=r"(r[2]), "=r"(r[3]) : "r"(addr));
}
__device__ __forceinline__ void ldsm2(uint32_t* r, uint32_t addr) {
    asm volatile("ldmatrix.sync.aligned.m8n8.x2.shared.b16 {%0,%1}, [%2];"
                 : "=r"(r[0]), "=r"(r[1]) : "r"(addr));
}
__device__ __forceinline__ void mma16816(float* d, const uint32_t* a, const uint32_t* b) {
    asm volatile("mma.sync.aligned.m16n8k16.row.col.f32.f16.f16.f32 "
                 "{%0,%1,%2,%3}, {%4,%5,%6,%7}, {%8,%9}, {%0,%1,%2,%3};"
                 : "+f"(d[0]), "+f"(d[1]), "+f"(d[2]), "+f"(d[3])
                 : "r"(a[0]), "r"(a[1]), "r"(a[2]), "r"(a[3]), "r"(b[0]), "r"(b[1]));
}

// ---------------------------------------------------------------------------

__global__ void k_setn(int n0) { g_n[0] = n0; }

__global__ void k_fill(int* g, int v, int P) {
    int i = blockIdx.x * blockDim.x + threadIdx.x;
    if (i < P) g[i] = v;
}

__global__ void k_scatter0(const int* __restrict__ coors, int n0) {
    int i = blockIdx.x * blockDim.x + threadIdx.x;
    if (i >= n0) return;
    int z = coors[i * 4 + 1];
    int y = coors[i * 4 + 2];
    int x = coors[i * 4 + 3];
    int l = (z * 128 + y) * 128 + x;
    g_linA[i] = l;
    g_gridA[l] = i;
}

__global__ void k_pairs(const int* __restrict__ lin, const int* __restrict__ grid,
                        const int* __restrict__ np, int S) {
    int n = *np;
    int i = blockIdx.x * blockDim.x + threadIdx.x;
    if (i >= n) return;
    int l = lin[i];
    int z = l / (S * S);
    int rem = l - z * S * S;
    int y = rem / S;
    int x = rem - y * S;
    int k = 0;
    #pragma unroll
    for (int dz = -1; dz <= 1; dz++)
        #pragma unroll
        for (int dy = -1; dy <= 1; dy++)
            #pragma unroll
            for (int dx = -1; dx <= 1; dx++) {
                int zz = z + dz, yy = y + dy, xx = x + dx;
                int v = -1;
                if (zz >= 0 && zz < S && yy >= 0 && yy < S && xx >= 0 && xx < S)
                    v = grid[(zz * S + yy) * S + xx];
                g_pairs[k * NMAX + i] = v;
                k++;
            }
}

// Weight blob: W[27,Cin,Cout] fp32 -> per-chunk SW128 images of W^T
// [Cout rows x 64 cols] fp16 single-limb. Chunk = (k, ci-chunk).
__global__ void k_wcvt(const float* __restrict__ W, unsigned char* __restrict__ blob,
                       int Cin, int CinP, int Cout) {
    int total = 27 * CinP * Cout;
    int idx = blockIdx.x * 256 + threadIdx.x;
    if (idx >= total) return;
    int ci = idx % CinP;
    int t = idx / CinP;
    int co = t % Cout;
    int k = t / Cout;
    float v = (ci < Cin) ? W[((size_t)k * Cin + ci) * Cout + co] : 0.f;
    __half h = __float2half_rn(v);
    int ch = ci >> 6, cic = ci & 63;
    int sw = (((cic >> 3) ^ (co & 7)) << 4) + (cic & 7) * 2;
    int NCH = CinP >> 6;
    size_t stageBase = (size_t)(k * NCH + ch) * (Cout * 128);
    *(__half*)(blob + stageBase + (size_t)co * 128 + sw) = h;
}

// ---------------------------------------------------------------------------
// Fused L0 conv1: Cin=3, Cout=64, writes fp16 table (CP=64), skips missing.
// ---------------------------------------------------------------------------
__global__ __launch_bounds__(256) void k_conv0(const float* __restrict__ feats,
                                               const float* __restrict__ W,
                                               __half* __restrict__ out,
                                               const int* __restrict__ np) {
    __shared__ float Ws[27 * 3 * 64];
    int n = *np;
    int tid = threadIdx.x;
    for (int e = tid; e < 27 * 3 * 64; e += 256) Ws[e] = W[e];
    __syncthreads();
    int r = blockIdx.x * 4 + (tid >> 6);
    int lane = tid & 63;
    if (r >= n) return;
    float acc = 0.f;
    #pragma unroll 1
    for (int k = 0; k < 27; k++) {
        int id = g_pairs[k * NMAX + r];
        if (id >= 0) {
            float f0 = feats[id * 3 + 0];
            float f1 = feats[id * 3 + 1];
            float f2 = feats[id * 3 + 2];
            const float* wk = Ws + k * 192;
            acc += f0 * wk[lane] + f1 * wk[64 + lane] + f2 * wk[128 + lane];
        }
    }
    out[(size_t)r * 64 + lane] = __float2half_rn(acc);
}

// ---------------------------------------------------------------------------
// mma.sync conv: 128-row tile x CoutS col slice, pure fp16, fp32 accumulate.
// 512 threads = 16 warps = 4 row-groups x 4 col-quarters.
// 2-stage cp.async pipeline, CPS 64-chunks per stage (Ctot % CPS == 0).
// ---------------------------------------------------------------------------
template <int NT>   // NT = CoutS/8
__global__ __launch_bounds__(512) void k_wconv(
    const __half* __restrict__ fin,
    const unsigned char* __restrict__ wblob,
    float* __restrict__ outF,
    __half* __restrict__ outH, int CP,
    const int* __restrict__ np, int Cin, int CinP, int CoutF, int CPS)
{
    const int NT4 = NT / 4;
    const int CoutS = NT * 8;
    const int WchunkS = CoutS * 128;
    int n = *np;
    int rowBase = blockIdx.x * 128;
    if (rowBase >= n) return;
    int colBase = blockIdx.y * CoutS;

    extern __shared__ __align__(1024) unsigned char sm[];
    const int AstageS = CPS * 16384;
    const int WstageS = CPS * WchunkS;
    const uint32_t Asm = smem_u32(sm);
    const uint32_t Wsm = Asm + 2 * AstageS;

    int tid = threadIdx.x;
    int wid = tid >> 5;
    int lane = tid & 31;

    const int NCH = CinP >> 6;
    const int Ctot = 27 * NCH;
    const int S = Ctot / CPS;       // exact by construction
    const int WchunkF = CoutF * 128;
    const int lastSub = ((Cin & 63) == 32) ? 2 : 4;

    // A-gather: 4 threads per row, each covers 2 x 16B per chunk
    int am = tid >> 2;        // 0..127 row
    int q = tid & 3;          // 16B slot group
    int r_g = rowBase + am;
    int curK = -1, curId = -1;

    float acc[2][NT4][4];
    #pragma unroll
    for (int mt = 0; mt < 2; mt++)
        #pragma unroll
        for (int j = 0; j < NT4; j++)
            #pragma unroll
            for (int p = 0; p < 4; p++) acc[mt][j][p] = 0.f;

    auto load = [&](int buf, int s) {
        for (int cc = 0; cc < CPS; cc++) {
            int g = s * CPS + cc;
            int k = g / NCH;
            if (k != curK) {
                curK = k;
                curId = (r_g < n) ? g_pairs[k * NMAX + r_g] : -1;
            }
            int ch = g - k * NCH;
            const unsigned char* src =
                (const unsigned char*)(fin + (size_t)(curId < 0 ? 0 : curId) * CinP + ch * 64);
            uint32_t dst = Asm + buf * AstageS + cc * 16384 + am * 128;
            int m7 = (am & 7) << 4;
            int sz = (curId >= 0) ? 16 : 0;
            #pragma unroll
            for (int j = 0; j < 2; j++) {
                int c = q * 2 + j;
                cp_async16(dst + ((c << 4) ^ m7), src + c * 16, sz);
            }
        }
        {
            const int hc1 = WchunkS >> 4;
            const int hc = CPS * hc1;
            uint32_t dst = Wsm + buf * WstageS;
            for (int e = tid; e < hc; e += 512) {
                int ci = e / hc1;
                int e2 = e - ci * hc1;
                int g = s * CPS + ci;
                const unsigned char* sp =
                    wblob + (size_t)g * WchunkF + (size_t)colBase * 128 + e2 * 16;
                cp_async16(dst + e * 16, sp, 16);
            }
        }
        cp_commit();
    };

    int rw = wid & 3;
    int cw = wid >> 2;
    int arow0 = rw * 32 + (lane & 15);
    int ac16 = (lane >> 4) & 1;
    int brow_l = lane & 7;
    int bc16 = (lane >> 3) & 1;

    load(0, 0);
    for (int s = 0; s < S; s++) {
        int b = s & 1;
        if (s + 1 < S) {
            load(b ^ 1, s + 1);
            asm volatile("cp.async.wait_group 1;\n");
        } else {
            asm volatile("cp.async.wait_group 0;\n");
        }
        __syncthreads();

        for (int cc = 0; cc < CPS; cc++) {
            int g = s * CPS + cc;
            int k = g / NCH;
            int ch = g - k * NCH;
            int nsub = (ch == NCH - 1) ? lastSub : 4;
            uint32_t AB = Asm + b * AstageS + cc * 16384;
            uint32_t WB = Wsm + b * WstageS + cc * WchunkS;
            #pragma unroll
            for (int chunk = 0; chunk < 4; chunk++) {
                if (chunk >= nsub) break;
                uint32_t ah[2][4];
                #pragma unroll
                for (int mt = 0; mt < 2; mt++) {
                    uint32_t off = (uint32_t)(arow0 + mt * 16) * 128 + chunk * 32 + ac16 * 16;
                    off ^= (off >> 3) & 0x70;
                    ldsm4(ah[mt], AB + off);
                }
                #pragma unroll
                for (int j = 0; j < NT4; j++) {
                    uint32_t off = (uint32_t)(cw * (NT4 * 8) + j * 8 + brow_l) * 128
                                 + chunk * 32 + bc16 * 16;
                    off ^= (off >> 3) & 0x70;
                    uint32_t bh[2];
                    ldsm2(bh, WB + off);
                    #pragma unroll
                    for (int mt = 0; mt < 2; mt++)
                        mma16816(acc[mt][j], ah[mt], bh);
                }
            }
        }
        __syncthreads();
    }

    int grp = lane >> 2, tg = lane & 3;
    #pragma unroll
    for (int mt = 0; mt < 2; mt++) {
        int r0 = rowBase + rw * 32 + mt * 16 + grp;
        #pragma unroll
        for (int half = 0; half < 2; half++) {
            int r = r0 + half * 8;
            if (r >= n) continue;
            #pragma unroll
            for (int j = 0; j < NT4; j++) {
                float d0 = acc[mt][j][half * 2 + 0];
                float d1 = acc[mt][j][half * 2 + 1];
                int c = colBase + cw * (NT4 * 8) + j * 8 + tg * 2;
                if (outF) {
                    float2 v; v.x = d0; v.y = d1;
                    *(float2*)(outF + (size_t)r * CoutF + c) = v;
                }
                if (outH) {
                    __half h0 = __float2half_rn(d0);
                    __half h1 = __float2half_rn(d1);
                    uint32_t hp = ((uint32_t)(*(unsigned short*)&h1) << 16)
                                | (uint32_t)(*(unsigned short*)&h0);
                    *(uint32_t*)(outH + (size_t)r * CP + c) = hp;
                }
            }
            if (outH && blockIdx.y == 0 && cw == 0) {
                for (int c = CoutF + tg * 2; c < CP; c += 8)
                    *(uint32_t*)(outH + (size_t)r * CP + c) = 0u;
            }
        }
    }
}

// ---------------------------------------------------------------------------
// Small-level scalar conv (n <= 512): 16 rows x 32 cols per block.
// ---------------------------------------------------------------------------
__global__ __launch_bounds__(256) void k_conv_small(const float* __restrict__ feats,
                                                    const float* __restrict__ W,
                                                    float* __restrict__ out,
                                                    const int* __restrict__ np,
                                                    int Cin, int Cout) {
    int n = *np;
    int rowBase = blockIdx.x * 16;
    if (rowBase >= n) return;
    int colBase = blockIdx.y * 32;

    __shared__ float As[16][33];
    __shared__ float Ws[32][33];

    int tid = threadIdx.x;
    int tm = tid >> 5;
    int tn = tid & 31;

    float acc0 = 0.f, acc1 = 0.f;

    for (int k = 0; k < 27; k++) {
        for (int c0 = 0; c0 < Cin; c0 += 32) {
            __syncthreads();
            {
                int e = tid;
                #pragma unroll
                for (int j = 0; j < 2; j++, e += 256) {
                    int m = e >> 5, c = e & 31;
                    int r = rowBase + m;
                    int id = (r < n) ? g_pairs[k * NMAX + r] : -1;
                    As[m][c] = (id >= 0) ? feats[(size_t)id * Cin + c0 + c] : 0.f;
                }
            }
            {
                const float* Wk = W + ((size_t)k * Cin + c0) * Cout + colBase;
                int e = tid;
                #pragma unroll
                for (int j = 0; j < 4; j++, e += 256) {
                    int kk = e >> 5, c = e & 31;
                    Ws[kk][c] = Wk[(size_t)kk * Cout + c];
                }
            }
            __syncthreads();
            #pragma unroll 8
            for (int kk = 0; kk < 32; kk++) {
                float w = Ws[kk][tn];
                acc0 += As[tm * 2][kk] * w;
                acc1 += As[tm * 2 + 1][kk] * w;
            }
        }
    }

    int r0 = rowBase + tm * 2;
    if (r0 < n)     out[(size_t)r0 * Cout + colBase + tn] = acc0;
    if (r0 + 1 < n) out[(size_t)(r0 + 1) * Cout + colBase + tn] = acc1;
}

// ---------------------------------------------------------------------------
// Pool structure kernels + pool with optional fp16 output table
// ---------------------------------------------------------------------------
__global__ void k_flags(const int* __restrict__ fineGrid, int S) {
    int Sc = S >> 1;
    int P = Sc * Sc * Sc;
    int p = blockIdx.x * blockDim.x + threadIdx.x;
    if (p >= P) return;
    int pz = p / (Sc * Sc);
    int rem = p - pz * Sc * Sc;
    int py = rem / Sc;
    int px = rem - py * Sc;
    int occ = 0;
    #pragma unroll
    for (int a = 0; a < 2; a++)
        #pragma unroll
        for (int b = 0; b < 2; b++)
            #pragma unroll
            for (int c = 0; c < 2; c++) {
                int l = ((2 * pz + a) * S + 2 * py + b) * S + 2 * px + c;
                if (fineGrid[l] >= 0) occ = 1;
            }
    g_flags[p] = occ;
}

__global__ void k_scanA(int P) {
    __shared__ int sh[256];
    int t = threadIdx.x;
    int base = blockIdx.x * 1024;
    int s = 0;
    #pragma unroll
    for (int j = 0; j < 4; j++) {
        int p = base + t * 4 + j;
        if (p < P) s += g_flags[p];
    }
    sh[t] = s;
    __syncthreads();
    for (int d = 128; d > 0; d >>= 1) {
        if (t < d) sh[t] += sh[t + d];
        __syncthreads();
    }
    if (t == 0) g_bsums[blockIdx.x] = sh[0];
}

__global__ void k_scanB(int nb, int Lnext) {
    __shared__ int sh[256];
    int t = threadIdx.x;
    int v = (t < nb) ? g_bsums[t] : 0;
    sh[t] = v;
    __syncthreads();
    for (int d = 1; d < 256; d <<= 1) {
        int x = (t >= d) ? sh[t - d] : 0;
        __syncthreads();
        sh[t] += x;
        __syncthreads();
    }
    if (t < nb) g_bsums[t] = sh[t] - v;
    if (t == 255) g_n[Lnext] = sh[255];
}

__global__ void k_scanC(int* __restrict__ coarseGrid, int* __restrict__ linNext, int P) {
    __shared__ int sh[256];
    int t = threadIdx.x;
    int base = blockIdx.x * 1024;
    int f[4];
    int s = 0;
    #pragma unroll
    for (int j = 0; j < 4; j++) {
        int p = base + t * 4 + j;
        f[j] = (p < P) ? g_flags[p] : 0;
        s += f[j];
    }
    int v = s;
    sh[t] = v;
    __syncthreads();
    for (int d = 1; d < 256; d <<= 1) {
        int x = (t >= d) ? sh[t - d] : 0;
        __syncthreads();
        sh[t] += x;
        __syncthreads();
    }
    int off = g_bsums[blockIdx.x] + sh[t] - v;
    #pragma unroll
    for (int j = 0; j < 4; j++) {
        int p = base + t * 4 + j;
        if (p >= P) break;
        if (f[j]) {
            coarseGrid[p] = off;
            linNext[off] = p;
            off++;
        } else {
            coarseGrid[p] = -1;
        }
    }
}

__global__ void k_pool2(const float* __restrict__ feats, float* __restrict__ out,
                        __half* __restrict__ oh,
                        const int* __restrict__ fineGrid, const int* __restrict__ linNext,
                        const int* __restrict__ np, int S, int C, int CP) {
    int row = blockIdx.x;
    if (row >= *np) return;
    int Sc = S >> 1;
    int p = linNext[row];
    int pz = p / (Sc * Sc);
    int rem = p - pz * Sc * Sc;
    int py = rem / Sc;
    int px = rem - py * Sc;
    int c = threadIdx.x;
    if (c < C) {
        float m = -3.4e38f;
        #pragma unroll
        for (int a = 0; a < 2; a++)
            #pragma unroll
            for (int b = 0; b < 2; b++)
                #pragma unroll
                for (int d = 0; d < 2; d++) {
                    int l = ((2 * pz + a) * S + 2 * py + b) * S + 2 * px + d;
                    int r = fineGrid[l];
                    if (r >= 0) m = fmaxf(m, feats[(size_t)r * C + c]);
                }
        out[(size_t)row * C + c] = m;
        if (CP) oh[(size_t)row * CP + c] = __float2half_rn(m);
    } else if (CP && c < CP) {
        oh[(size_t)row * CP + c] = __float2half_rn(0.f);
    }
}

// ---------------------------------------------------------------------------

static inline int ceildiv(int a, int b) { return (a + b - 1) / b; }
static inline int pad64(int c) { return (c + 63) & ~63; }

static void launch_wconv(const __half* fin, const unsigned char* wb, float* outF,
                         __half* oh, int CP, const int* np, int Cin, int CinP,
                         int Cout, int nBound, int gy, int cps) {
    int CoutS = Cout / gy;
    int NT = CoutS / 8;
    dim3 g(ceildiv(nBound, 128), gy), b(512);
    int smem = 2 * cps * 16384 + 2 * cps * CoutS * 128;
    switch (NT) {
        case 4:
            cudaFuncSetAttribute(k_wconv<4>, cudaFuncAttributeMaxDynamicSharedMemorySize, smem);
            k_wconv<4><<<g, b, smem>>>(fin, wb, outF, oh, CP, np, Cin, CinP, Cout, cps);
            break;
        case 8:
            cudaFuncSetAttribute(k_wconv<8>, cudaFuncAttributeMaxDynamicSharedMemorySize, smem);
            k_wconv<8><<<g, b, smem>>>(fin, wb, outF, oh, CP, np, Cin, CinP, Cout, cps);
            break;
        case 12:
            cudaFuncSetAttribute(k_wconv<12>, cudaFuncAttributeMaxDynamicSharedMemorySize, smem);
            k_wconv<12><<<g, b, smem>>>(fin, wb, outF, oh, CP, np, Cin, CinP, Cout, cps);
            break;
        case 16:
            cudaFuncSetAttribute(k_wconv<16>, cudaFuncAttributeMaxDynamicSharedMemorySize, smem);
            k_wconv<16><<<g, b, smem>>>(fin, wb, outF, oh, CP, np, Cin, CinP, Cout, cps);
            break;
    }
}

extern "C" void kernel_launch(void* const* d_in, const int* in_sizes, int n_in,
                              void* d_out, int out_size) {
    const float* feat_in = (const float*)d_in[0];
    const int*   coors   = (const int*)d_in[1];
    const float* w[14];
    for (int i = 0; i < 14; i++) w[i] = (const float*)d_in[3 + i];

    int n0 = in_sizes[0] / 3;

    float *fA, *fB;
    __half *t1, *t2;
    unsigned char* wblob;
    int *gA, *gB, *lA, *lB, *pn;
    cudaGetSymbolAddress((void**)&fA, g_featA);
    cudaGetSymbolAddress((void**)&fB, g_featB);
    cudaGetSymbolAddress((void**)&t1, g_fh1);
    cudaGetSymbolAddress((void**)&t2, g_fh2);
    cudaGetSymbolAddress((void**)&wblob, g_wblob);
    cudaGetSymbolAddress((void**)&gA, g_gridA);
    cudaGetSymbolAddress((void**)&gB, g_gridB);
    cudaGetSymbolAddress((void**)&lA, g_linA);
    cudaGetSymbolAddress((void**)&lB, g_linB);
    cudaGetSymbolAddress((void**)&pn, g_n);

    const int S[7]  = {128, 64, 32, 16, 8, 4, 2};
    int NB[7];
    NB[0] = n0;
    NB[1] = n0 < (64 * 64 * 64) ? n0 : (64 * 64 * 64);
    NB[2] = 32 * 32 * 32;
    NB[3] = 16 * 16 * 16;
    NB[4] = 8 * 8 * 8;
    NB[5] = 4 * 4 * 4;
    NB[6] = 2 * 2 * 2;
    const int Cin1[7]  = {3, 64, 96, 128, 160, 192, 224};
    const int Cout1[7] = {64, 96, 128, 160, 192, 224, 256};

    // MMA-path layers (0..7 == L0c1..L3c2); layer 0 handled by k_conv0
    const int LCin[8]  = {3, 64, 64, 96, 96, 128, 128, 160};
    const int LCinP[8] = {64, 64, 64, 128, 128, 128, 128, 192};
    const int LCout[8] = {64, 64, 96, 96, 128, 128, 160, 160};
    // chunks-per-stage: keep >=2 blocks/SM except L3c2 (1-wave level anyway)
    const int LCPS[8]  = {1, 1, 1, 2, 1, 1, 2, 3};
    size_t woff[9];
    woff[0] = 0;
    for (int i = 0; i < 8; i++)
        woff[i + 1] = woff[i] + (size_t)27 * (LCinP[i] / 64) * LCout[i] * 128;

    // ---- weight blob (layers 1..7) + level-0 structure ----
    for (int i = 1; i < 8; i++) {
        int total = 27 * LCinP[i] * LCout[i];
        k_wcvt<<<ceildiv(total, 256), 256>>>(w[i], wblob + woff[i],
                                             LCin[i], LCinP[i], LCout[i]);
    }
    k_setn<<<1, 1>>>(n0);
    k_fill<<<ceildiv(GRID_CELLS, 256), 256>>>(gA, -1, GRID_CELLS);
    k_scatter0<<<ceildiv(n0, 256), 256>>>(coors, n0);

    int* linCur = lA;
    int* gridCur = gA;
    int* linNxt = lB;
    int* gridNxt = gB;

    // ---- MMA levels 0..3 ----
    for (int L = 0; L < 4; L++) {
        const int* np = pn + L;
        k_pairs<<<ceildiv(NB[L], 256), 256>>>(linCur, gridCur, np, S[L]);

        int li1 = 2 * L, li2 = 2 * L + 1;
        int gy = (L == 3) ? 5 : 1;
        if (L == 0) {
            k_conv0<<<ceildiv(NB[0], 4), 256>>>(feat_in, w[0], t2, np);
        } else {
            launch_wconv(t1, wblob + woff[li1], nullptr, t2, LCinP[li2],
                         np, LCin[li1], LCinP[li1], LCout[li1], NB[L], gy, LCPS[li1]);
        }
        launch_wconv(t2, wblob + woff[li2], fA, nullptr, 0,
                     np, LCin[li2], LCinP[li2], LCout[li2], NB[L], gy, LCPS[li2]);

        {
            int Sc = S[L] >> 1, P = Sc * Sc * Sc, nb = ceildiv(P, 1024);
            k_flags<<<ceildiv(P, 256), 256>>>(gridCur, S[L]);
            k_scanA<<<nb, 256>>>(P);
            k_scanB<<<1, 256>>>(nb, L + 1);
            k_scanC<<<nb, 256>>>(gridNxt, linNxt, P);
            int C = LCout[li2];
            int CP = (L < 3) ? pad64(C) : 0;
            int thr = CP ? CP : C;
            k_pool2<<<NB[L + 1], thr>>>(fA, fB, t1, gridCur, linNxt,
                                        pn + L + 1, S[L], C, CP);
        }
        int* t;
        t = linCur; linCur = linNxt; linNxt = t;
        t = gridCur; gridCur = gridNxt; gridNxt = t;
    }

    // ---- FFMA levels 4..6 (pool L3 output in fB) ----
    const float* cur = fB;
    for (int L = 4; L < 7; L++) {
        const int* np = pn + L;
        k_pairs<<<ceildiv(NB[L], 256), 256>>>(linCur, gridCur, np, S[L]);
        int ci1 = Cin1[L], co1 = Cout1[L];
        float* o1 = (cur == fB) ? fA : fB;
        {
            dim3 g(ceildiv(NB[L], 16), co1 / 32), b(256);
            k_conv_small<<<g, b>>>(cur, w[2 * L], o1, np, ci1, co1);
        }
        float* o2 = (L == 6) ? (float*)d_out : ((o1 == fA) ? fB : fA);
        {
            dim3 g(ceildiv(NB[L], 16), co1 / 32), b(256);
            k_conv_small<<<g, b>>>(o1, w[2 * L + 1], o2, np, co1, co1);
        }
        cur = o2;
        if (L < 6) {
            int Sc = S[L] >> 1, P = Sc * Sc * Sc, nb = ceildiv(P, 1024);
            k_flags<<<ceildiv(P, 256), 256>>>(gridCur, S[L]);
            k_scanA<<<nb, 256>>>(P);
            k_scanB<<<1, 256>>>(nb, L + 1);
            k_scanC<<<nb, 256>>>(gridNxt, linNxt, P);
            float* po = (cur == fA) ? fB : fA;
            k_pool2<<<NB[L + 1], co1>>>(cur, po, nullptr, gridCur, linNxt,
                                        pn + L + 1, S[L], co1, 0);
            cur = po;
            int* t;
            t = linCur; linCur = linNxt; linNxt = t;
            t = gridCur; gridCur = gridNxt; gridNxt = t;
        }
    }
}

// round 16
// speedup vs baseline: 1.8881x; 1.8425x over previous
#include <cuda_runtime.h>
#include <cuda_fp16.h>
#include <cstdint>

// ---------------------------------------------------------------------------
// Sparse submanifold 3D conv backbone, batch=1, 128^3 -> 2^3.
// L0 conv1 (Cin=3): neighbor-skipping scalar, writes fp16 feature table.
// L0c2..L3: mma.sync pure fp16 (fp32 accum), 1 chunk per pipeline stage
// (R13 structure). HALF template skips the zero upper half of the last
// K-chunk for layers with Cin % 64 == 32 (exact).
// Levels 4-6 (n <= 512): k-split scalar conv (grid.z=27) + atomicAdd.
// ---------------------------------------------------------------------------

#define NMAX 100000
#define GRID_CELLS (1 << 21)
#define FLAGS_MAX (1 << 18)

__device__ int   g_n[8];
__device__ int   g_linA[NMAX];
__device__ int   g_linB[NMAX];
__device__ int   g_gridA[GRID_CELLS];
__device__ int   g_gridB[GRID_CELLS];
__device__ int   g_pairs[27 * NMAX];
__device__ int   g_flags[FLAGS_MAX];
__device__ int   g_bsums[256];
__device__ __align__(1024) float g_featA[10000000];
__device__ __align__(1024) float g_featB[10000000];
// fp16 feature tables: t1 = conv1 input, t2 = conv2 input
__device__ __align__(1024) __half g_fh1[12000000];
__device__ __align__(1024) __half g_fh2[12000000];
// pre-swizzled, transposed fp16 weight blob (layers 1..7)
__device__ __align__(1024) unsigned char g_wblob[16 * 1024 * 1024];

// ---------------------------------------------------------------------------

__device__ __forceinline__ void cp_async16(uint32_t dst, const void* src, int srcBytes) {
    asm volatile("cp.async.cg.shared.global [%0], [%1], 16, %2;\n"
                 :: "r"(dst), "l"(src), "r"(srcBytes));
}
__device__ __forceinline__ void cp_commit() {
    asm volatile("cp.async.commit_group;\n");
}
__device__ __forceinline__ uint32_t smem_u32(const void* p) {
    uint32_t a;
    asm("{ .reg .u64 t; cvta.to.shared.u64 t, %1; cvt.u32.u64 %0, t; }" : "=r"(a) : "l"(p));
    return a;
}
__device__ __forceinline__ void ldsm4(uint32_t* r, uint32_t addr) {
    asm volatile("ldmatrix.sync.aligned.m8n8.x4.shared.b16 {%0,%1,%2,%3}, [%4];"
                 : "=r"(r[0]), "=r"(r[1]), "=r"(r[2]), "=r"(r[3]) : "r"(addr));
}
__device__ __forceinline__ void ldsm2(uint32_t* r, uint32_t addr) {
    asm volatile("ldmatrix.sync.aligned.m8n8.x2.shared.b16 {%0,%1}, [%2];"
                 : "=r"(r[0]), "=r"(r[1]) : "r"(addr));
}
__device__ __forceinline__ void mma16816(float* d, const uint32_t* a, const uint32_t* b) {
    asm volatile("mma.sync.aligned.m16n8k16.row.col.f32.f16.f16.f32 "
                 "{%0,%1,%2,%3}, {%4,%5,%6,%7}, {%8,%9}, {%0,%1,%2,%3};"
                 : "+f"(d[0]), "+f"(d[1]), "+f"(d[2]), "+f"(d[3])
                 : "r"(a[0]), "r"(a[1]), "r"(a[2]), "r"(a[3]), "r"(b[0]), "r"(b[1]));
}

// ---------------------------------------------------------------------------

__global__ void k_setn(int n0) { g_n[0] = n0; }

__global__ void k_fill(int* g, int v, int P) {
    int i = blockIdx.x * blockDim.x + threadIdx.x;
    if (i < P) g[i] = v;
}

__global__ void k_scatter0(const int* __restrict__ coors, int n0) {
    int i = blockIdx.x * blockDim.x + threadIdx.x;
    if (i >= n0) return;
    int z = coors[i * 4 + 1];
    int y = coors[i * 4 + 2];
    int x = coors[i * 4 + 3];
    int l = (z * 128 + y) * 128 + x;
    g_linA[i] = l;
    g_gridA[l] = i;
}

__global__ void k_pairs(const int* __restrict__ lin, const int* __restrict__ grid,
                        const int* __restrict__ np, int S) {
    int n = *np;
    int i = blockIdx.x * blockDim.x + threadIdx.x;
    if (i >= n) return;
    int l = lin[i];
    int z = l / (S * S);
    int rem = l - z * S * S;
    int y = rem / S;
    int x = rem - y * S;
    int k = 0;
    #pragma unroll
    for (int dz = -1; dz <= 1; dz++)
        #pragma unroll
        for (int dy = -1; dy <= 1; dy++)
            #pragma unroll
            for (int dx = -1; dx <= 1; dx++) {
                int zz = z + dz, yy = y + dy, xx = x + dx;
                int v = -1;
                if (zz >= 0 && zz < S && yy >= 0 && yy < S && xx >= 0 && xx < S)
                    v = grid[(zz * S + yy) * S + xx];
                g_pairs[k * NMAX + i] = v;
                k++;
            }
}

// Weight blob: W[27,Cin,Cout] fp32 -> per-chunk SW128 images of W^T
// [Cout rows x 64 cols] fp16. Chunk = (k, ci-chunk).
__global__ void k_wcvt(const float* __restrict__ W, unsigned char* __restrict__ blob,
                       int Cin, int CinP, int Cout) {
    int total = 27 * CinP * Cout;
    int idx = blockIdx.x * 256 + threadIdx.x;
    if (idx >= total) return;
    int ci = idx % CinP;
    int t = idx / CinP;
    int co = t % Cout;
    int k = t / Cout;
    float v = (ci < Cin) ? W[((size_t)k * Cin + ci) * Cout + co] : 0.f;
    __half h = __float2half_rn(v);
    int ch = ci >> 6, cic = ci & 63;
    int sw = (((cic >> 3) ^ (co & 7)) << 4) + (cic & 7) * 2;
    int NCH = CinP >> 6;
    size_t stageBase = (size_t)(k * NCH + ch) * (Cout * 128);
    *(__half*)(blob + stageBase + (size_t)co * 128 + sw) = h;
}

// ---------------------------------------------------------------------------
// Fused L0 conv1: Cin=3, Cout=64, writes fp16 table (CP=64), skips missing.
// ---------------------------------------------------------------------------
__global__ __launch_bounds__(256) void k_conv0(const float* __restrict__ feats,
                                               const float* __restrict__ W,
                                               __half* __restrict__ out,
                                               const int* __restrict__ np) {
    __shared__ float Ws[27 * 3 * 64];
    int n = *np;
    int tid = threadIdx.x;
    for (int e = tid; e < 27 * 3 * 64; e += 256) Ws[e] = W[e];
    __syncthreads();
    int r = blockIdx.x * 4 + (tid >> 6);
    int lane = tid & 63;
    if (r >= n) return;
    float acc = 0.f;
    #pragma unroll 1
    for (int k = 0; k < 27; k++) {
        int id = g_pairs[k * NMAX + r];
        if (id >= 0) {
            float f0 = feats[id * 3 + 0];
            float f1 = feats[id * 3 + 1];
            float f2 = feats[id * 3 + 2];
            const float* wk = Ws + k * 192;
            acc += f0 * wk[lane] + f1 * wk[64 + lane] + f2 * wk[128 + lane];
        }
    }
    out[(size_t)r * 64 + lane] = __float2half_rn(acc);
}

// ---------------------------------------------------------------------------
// mma.sync conv: 128-row tile x CoutS col slice, pure fp16, fp32 accumulate.
// 512 threads = 16 warps = 4 row-groups x 4 col-quarters.
// 2-stage cp.async pipeline, 1 K=64 chunk per stage (R13 structure).
// HALF: skip chunks 2-3 (zero cols) of the last ci-chunk of each k.
// ---------------------------------------------------------------------------
template <int NT, bool HALF>   // NT = CoutS/8
__global__ __launch_bounds__(512) void k_wconv(
    const __half* __restrict__ fin,
    const unsigned char* __restrict__ wblob,
    float* __restrict__ outF,
    __half* __restrict__ outH, int CP,
    const int* __restrict__ np, int CinP, int CoutF)
{
    const int NT4 = NT / 4;
    const int CoutS = NT * 8;
    const int WstageS = CoutS * 128;
    int n = *np;
    int rowBase = blockIdx.x * 128;
    if (rowBase >= n) return;
    int colBase = blockIdx.y * CoutS;

    extern __shared__ __align__(1024) unsigned char sm[];
    const uint32_t Asm = smem_u32(sm);        // 2 stages x 16KB
    const uint32_t Wsm = Asm + 2 * 16384;

    int tid = threadIdx.x;
    int wid = tid >> 5;
    int lane = tid & 31;

    const int NCH = CinP >> 6;
    const int S = 27 * NCH;
    const int WstageF = CoutF * 128;

    // A-gather: 4 threads per row, each loads 2 x 16B chunks
    int am = tid >> 2;        // 0..127 row
    int q = tid & 3;          // chunk group
    int r_g = rowBase + am;
    int curK = -1, curId = -1;

    float acc[2][NT4][4];
    #pragma unroll
    for (int mt = 0; mt < 2; mt++)
        #pragma unroll
        for (int j = 0; j < NT4; j++)
            #pragma unroll
            for (int p = 0; p < 4; p++) acc[mt][j][p] = 0.f;

    auto load = [&](int buf, int s) {
        int k = s / NCH;
        int ch = s - k * NCH;
        if (k != curK) {
            curK = k;
            curId = (r_g < n) ? g_pairs[k * NMAX + r_g] : -1;
        }
        {
            const unsigned char* src =
                (const unsigned char*)(fin + (size_t)(curId < 0 ? 0 : curId) * CinP + ch * 64);
            uint32_t dst = Asm + buf * 16384 + am * 128;
            int m7 = (am & 7) << 4;
            int sz = (curId >= 0) ? 16 : 0;
            #pragma unroll
            for (int c = q * 2; c < q * 2 + 2; c++)
                cp_async16(dst + ((c << 4) ^ m7), src + c * 16, sz);
        }
        {
            const unsigned char* src = wblob + (size_t)s * WstageF
                                     + (size_t)colBase * 128;
            const int hc = (CoutS * 128) >> 4;
            uint32_t dst = Wsm + buf * WstageS;
            for (int e = tid; e < hc; e += 512)
                cp_async16(dst + e * 16, src + e * 16, 16);
        }
        cp_commit();
    };

    int rw = wid & 3;
    int cw = wid >> 2;
    int arow0 = rw * 32 + (lane & 15);
    int ac16 = (lane >> 4) & 1;
    int brow_l = lane & 7;
    int bc16 = (lane >> 3) & 1;

    load(0, 0);
    for (int s = 0; s < S; s++) {
        int b = s & 1;
        if (s + 1 < S) {
            load(b ^ 1, s + 1);
            asm volatile("cp.async.wait_group 1;\n");
        } else {
            asm volatile("cp.async.wait_group 0;\n");
        }
        __syncthreads();

        uint32_t AhB = Asm + b * 16384;
        uint32_t WhB = Wsm + b * WstageS;
        bool full = true;
        if (HALF) {
            int k2 = s / NCH;
            full = (s - k2 * NCH) != (NCH - 1);
        }

        #pragma unroll
        for (int chunk = 0; chunk < 4; chunk++) {
            if (chunk < 2 || full) {
                uint32_t ah[2][4];
                #pragma unroll
                for (int mt = 0; mt < 2; mt++) {
                    uint32_t off = (uint32_t)(arow0 + mt * 16) * 128 + chunk * 32 + ac16 * 16;
                    off ^= (off >> 3) & 0x70;
                    ldsm4(ah[mt], AhB + off);
                }
                #pragma unroll
                for (int j = 0; j < NT4; j++) {
                    uint32_t off = (uint32_t)(cw * (NT4 * 8) + j * 8 + brow_l) * 128
                                 + chunk * 32 + bc16 * 16;
                    off ^= (off >> 3) & 0x70;
                    uint32_t bh[2];
                    ldsm2(bh, WhB + off);
                    #pragma unroll
                    for (int mt = 0; mt < 2; mt++)
                        mma16816(acc[mt][j], ah[mt], bh);
                }
            }
        }
        __syncthreads();
    }

    int grp = lane >> 2, tg = lane & 3;
    #pragma unroll
    for (int mt = 0; mt < 2; mt++) {
        int r0 = rowBase + rw * 32 + mt * 16 + grp;
        #pragma unroll
        for (int half = 0; half < 2; half++) {
            int r = r0 + half * 8;
            if (r >= n) continue;
            #pragma unroll
            for (int j = 0; j < NT4; j++) {
                float d0 = acc[mt][j][half * 2 + 0];
                float d1 = acc[mt][j][half * 2 + 1];
                int c = colBase + cw * (NT4 * 8) + j * 8 + tg * 2;
                if (outF) {
                    float2 v; v.x = d0; v.y = d1;
                    *(float2*)(outF + (size_t)r * CoutF + c) = v;
                }
                if (outH) {
                    __half h0 = __float2half_rn(d0);
                    __half h1 = __float2half_rn(d1);
                    uint32_t hp = ((uint32_t)(*(unsigned short*)&h1) << 16)
                                | (uint32_t)(*(unsigned short*)&h0);
                    *(uint32_t*)(outH + (size_t)r * CP + c) = hp;
                }
            }
            if (outH && blockIdx.y == 0 && cw == 0) {
                for (int c = CoutF + tg * 2; c < CP; c += 8)
                    *(uint32_t*)(outH + (size_t)r * CP + c) = 0u;
            }
        }
    }
}

// ---------------------------------------------------------------------------
// Small-level conv, k-split: grid (rows/16, Cout/32, 27). Each block handles
// one kernel offset; partials atomicAdd'ed into zero-initialized out.
// ---------------------------------------------------------------------------
__global__ __launch_bounds__(256) void k_conv_small2(const float* __restrict__ feats,
                                                     const float* __restrict__ W,
                                                     float* __restrict__ out,
                                                     const int* __restrict__ np,
                                                     int Cin, int Cout) {
    int n = *np;
    int rowBase = blockIdx.x * 16;
    if (rowBase >= n) return;
    int colBase = blockIdx.y * 32;
    int k = blockIdx.z;

    __shared__ float As[16][33];
    __shared__ float Ws[32][33];
    __shared__ int sIdx[16];

    int tid = threadIdx.x;
    int tm = tid >> 5;
    int tn = tid & 31;

    if (tid < 16) {
        int r = rowBase + tid;
        sIdx[tid] = (r < n) ? g_pairs[k * NMAX + r] : -1;
    }

    float acc0 = 0.f, acc1 = 0.f;

    for (int c0 = 0; c0 < Cin; c0 += 32) {
        __syncthreads();
        {
            int e = tid;
            #pragma unroll
            for (int j = 0; j < 2; j++, e += 256) {
                int m = e >> 5, c = e & 31;
                int id = sIdx[m];
                As[m][c] = (id >= 0) ? feats[(size_t)id * Cin + c0 + c] : 0.f;
            }
        }
        {
            const float* Wk = W + ((size_t)k * Cin + c0) * Cout + colBase;
            int e = tid;
            #pragma unroll
            for (int j = 0; j < 4; j++, e += 256) {
                int kk = e >> 5, c = e & 31;
                Ws[kk][c] = Wk[(size_t)kk * Cout + c];
            }
        }
        __syncthreads();
        #pragma unroll 8
        for (int kk = 0; kk < 32; kk++) {
            float w = Ws[kk][tn];
            acc0 += As[tm * 2][kk] * w;
            acc1 += As[tm * 2 + 1][kk] * w;
        }
    }

    int r0 = rowBase + tm * 2;
    if (r0 < n)     atomicAdd(&out[(size_t)r0 * Cout + colBase + tn], acc0);
    if (r0 + 1 < n) atomicAdd(&out[(size_t)(r0 + 1) * Cout + colBase + tn], acc1);
}

// ---------------------------------------------------------------------------
// Pool structure kernels + pool with optional fp16 output table
// ---------------------------------------------------------------------------
__global__ void k_flags(const int* __restrict__ fineGrid, int S) {
    int Sc = S >> 1;
    int P = Sc * Sc * Sc;
    int p = blockIdx.x * blockDim.x + threadIdx.x;
    if (p >= P) return;
    int pz = p / (Sc * Sc);
    int rem = p - pz * Sc * Sc;
    int py = rem / Sc;
    int px = rem - py * Sc;
    int occ = 0;
    #pragma unroll
    for (int a = 0; a < 2; a++)
        #pragma unroll
        for (int b = 0; b < 2; b++)
            #pragma unroll
            for (int c = 0; c < 2; c++) {
                int l = ((2 * pz + a) * S + 2 * py + b) * S + 2 * px + c;
                if (fineGrid[l] >= 0) occ = 1;
            }
    g_flags[p] = occ;
}

__global__ void k_scanA(int P) {
    __shared__ int sh[256];
    int t = threadIdx.x;
    int base = blockIdx.x * 1024;
    int s = 0;
    #pragma unroll
    for (int j = 0; j < 4; j++) {
        int p = base + t * 4 + j;
        if (p < P) s += g_flags[p];
    }
    sh[t] = s;
    __syncthreads();
    for (int d = 128; d > 0; d >>= 1) {
        if (t < d) sh[t] += sh[t + d];
        __syncthreads();
    }
    if (t == 0) g_bsums[blockIdx.x] = sh[0];
}

__global__ void k_scanB(int nb, int Lnext) {
    __shared__ int sh[256];
    int t = threadIdx.x;
    int v = (t < nb) ? g_bsums[t] : 0;
    sh[t] = v;
    __syncthreads();
    for (int d = 1; d < 256; d <<= 1) {
        int x = (t >= d) ? sh[t - d] : 0;
        __syncthreads();
        sh[t] += x;
        __syncthreads();
    }
    if (t < nb) g_bsums[t] = sh[t] - v;
    if (t == 255) g_n[Lnext] = sh[255];
}

__global__ void k_scanC(int* __restrict__ coarseGrid, int* __restrict__ linNext, int P) {
    __shared__ int sh[256];
    int t = threadIdx.x;
    int base = blockIdx.x * 1024;
    int f[4];
    int s = 0;
    #pragma unroll
    for (int j = 0; j < 4; j++) {
        int p = base + t * 4 + j;
        f[j] = (p < P) ? g_flags[p] : 0;
        s += f[j];
    }
    int v = s;
    sh[t] = v;
    __syncthreads();
    for (int d = 1; d < 256; d <<= 1) {
        int x = (t >= d) ? sh[t - d] : 0;
        __syncthreads();
        sh[t] += x;
        __syncthreads();
    }
    int off = g_bsums[blockIdx.x] + sh[t] - v;
    #pragma unroll
    for (int j = 0; j < 4; j++) {
        int p = base + t * 4 + j;
        if (p >= P) break;
        if (f[j]) {
            coarseGrid[p] = off;
            linNext[off] = p;
            off++;
        } else {
            coarseGrid[p] = -1;
        }
    }
}

__global__ void k_pool2(const float* __restrict__ feats, float* __restrict__ out,
                        __half* __restrict__ oh,
                        const int* __restrict__ fineGrid, const int* __restrict__ linNext,
                        const int* __restrict__ np, int S, int C, int CP) {
    int row = blockIdx.x;
    if (row >= *np) return;
    int Sc = S >> 1;
    int p = linNext[row];
    int pz = p / (Sc * Sc);
    int rem = p - pz * Sc * Sc;
    int py = rem / Sc;
    int px = rem - py * Sc;
    int c = threadIdx.x;
    if (c < C) {
        float m = -3.4e38f;
        #pragma unroll
        for (int a = 0; a < 2; a++)
            #pragma unroll
            for (int b = 0; b < 2; b++)
                #pragma unroll
                for (int d = 0; d < 2; d++) {
                    int l = ((2 * pz + a) * S + 2 * py + b) * S + 2 * px + d;
                    int r = fineGrid[l];
                    if (r >= 0) m = fmaxf(m, feats[(size_t)r * C + c]);
                }
        out[(size_t)row * C + c] = m;
        if (CP) oh[(size_t)row * CP + c] = __float2half_rn(m);
    } else if (CP && c < CP) {
        oh[(size_t)row * CP + c] = __float2half_rn(0.f);
    }
}

// ---------------------------------------------------------------------------

static inline int ceildiv(int a, int b) { return (a + b - 1) / b; }
static inline int pad64(int c) { return (c + 63) & ~63; }

static void launch_wconv(const __half* fin, const unsigned char* wb, float* outF,
                         __half* oh, int CP, const int* np, int CinP, int Cout,
                         int nBound, int gy, bool half) {
    int CoutS = Cout / gy;
    int NT = CoutS / 8;
    dim3 g(ceildiv(nBound, 128), gy), b(512);
    int smem = 2 * 16384 + 2 * CoutS * 128;
#define LW_CASE(NTV)                                                                     \
    if (half) {                                                                          \
        cudaFuncSetAttribute(k_wconv<NTV, true>,                                         \
                             cudaFuncAttributeMaxDynamicSharedMemorySize, smem);         \
        k_wconv<NTV, true><<<g, b, smem>>>(fin, wb, outF, oh, CP, np, CinP, Cout);       \
    } else {                                                                             \
        cudaFuncSetAttribute(k_wconv<NTV, false>,                                        \
                             cudaFuncAttributeMaxDynamicSharedMemorySize, smem);         \
        k_wconv<NTV, false><<<g, b, smem>>>(fin, wb, outF, oh, CP, np, CinP, Cout);      \
    }
    switch (NT) {
        case 4:  LW_CASE(4)  break;
        case 8:  LW_CASE(8)  break;
        case 12: LW_CASE(12) break;
        case 16: LW_CASE(16) break;
    }
#undef LW_CASE
}

extern "C" void kernel_launch(void* const* d_in, const int* in_sizes, int n_in,
                              void* d_out, int out_size) {
    const float* feat_in = (const float*)d_in[0];
    const int*   coors   = (const int*)d_in[1];
    const float* w[14];
    for (int i = 0; i < 14; i++) w[i] = (const float*)d_in[3 + i];

    int n0 = in_sizes[0] / 3;

    float *fA, *fB;
    __half *t1, *t2;
    unsigned char* wblob;
    int *gA, *gB, *lA, *lB, *pn;
    cudaGetSymbolAddress((void**)&fA, g_featA);
    cudaGetSymbolAddress((void**)&fB, g_featB);
    cudaGetSymbolAddress((void**)&t1, g_fh1);
    cudaGetSymbolAddress((void**)&t2, g_fh2);
    cudaGetSymbolAddress((void**)&wblob, g_wblob);
    cudaGetSymbolAddress((void**)&gA, g_gridA);
    cudaGetSymbolAddress((void**)&gB, g_gridB);
    cudaGetSymbolAddress((void**)&lA, g_linA);
    cudaGetSymbolAddress((void**)&lB, g_linB);
    cudaGetSymbolAddress((void**)&pn, g_n);

    const int S[7]  = {128, 64, 32, 16, 8, 4, 2};
    int NB[7];
    NB[0] = n0;
    NB[1] = n0 < (64 * 64 * 64) ? n0 : (64 * 64 * 64);
    NB[2] = 32 * 32 * 32;
    NB[3] = 16 * 16 * 16;
    NB[4] = 8 * 8 * 8;
    NB[5] = 4 * 4 * 4;
    NB[6] = 2 * 2 * 2;
    const int Cin1[7]  = {3, 64, 96, 128, 160, 192, 224};
    const int Cout1[7] = {64, 96, 128, 160, 192, 224, 256};

    // MMA-path layers (0..7 == L0c1..L3c2); layer 0 handled by k_conv0
    const int LCin[8]  = {3, 64, 64, 96, 96, 128, 128, 160};
    const int LCinP[8] = {64, 64, 64, 128, 128, 128, 128, 192};
    const int LCout[8] = {64, 64, 96, 96, 128, 128, 160, 160};
    size_t woff[9];
    woff[0] = 0;
    for (int i = 0; i < 8; i++)
        woff[i + 1] = woff[i] + (size_t)27 * (LCinP[i] / 64) * LCout[i] * 128;

    // ---- weight blob (layers 1..7) + level-0 structure ----
    for (int i = 1; i < 8; i++) {
        int total = 27 * LCinP[i] * LCout[i];
        k_wcvt<<<ceildiv(total, 256), 256>>>(w[i], wblob + woff[i],
                                             LCin[i], LCinP[i], LCout[i]);
    }
    k_setn<<<1, 1>>>(n0);
    k_fill<<<ceildiv(GRID_CELLS, 256), 256>>>(gA, -1, GRID_CELLS);
    k_scatter0<<<ceildiv(n0, 256), 256>>>(coors, n0);

    int* linCur = lA;
    int* gridCur = gA;
    int* linNxt = lB;
    int* gridNxt = gB;

    // ---- MMA levels 0..3 ----
    for (int L = 0; L < 4; L++) {
        const int* np = pn + L;
        k_pairs<<<ceildiv(NB[L], 256), 256>>>(linCur, gridCur, np, S[L]);

        int li1 = 2 * L, li2 = 2 * L + 1;
        int gy = (L == 3) ? 5 : 1;
        if (L == 0) {
            k_conv0<<<ceildiv(NB[0], 4), 256>>>(feat_in, w[0], t2, np);
        } else {
            launch_wconv(t1, wblob + woff[li1], nullptr, t2, LCinP[li2],
                         np, LCinP[li1], LCout[li1], NB[L], gy,
                         (LCin[li1] & 63) == 32);
        }
        launch_wconv(t2, wblob + woff[li2], fA, nullptr, 0,
                     np, LCinP[li2], LCout[li2], NB[L], gy,
                     (LCin[li2] & 63) == 32);

        {
            int Sc = S[L] >> 1, P = Sc * Sc * Sc, nb = ceildiv(P, 1024);
            k_flags<<<ceildiv(P, 256), 256>>>(gridCur, S[L]);
            k_scanA<<<nb, 256>>>(P);
            k_scanB<<<1, 256>>>(nb, L + 1);
            k_scanC<<<nb, 256>>>(gridNxt, linNxt, P);
            int C = LCout[li2];
            int CP = (L < 3) ? pad64(C) : 0;
            int thr = CP ? CP : C;
            k_pool2<<<NB[L + 1], thr>>>(fA, fB, t1, gridCur, linNxt,
                                        pn + L + 1, S[L], C, CP);
        }
        int* t;
        t = linCur; linCur = linNxt; linNxt = t;
        t = gridCur; gridCur = gridNxt; gridNxt = t;
    }

    // ---- k-split scalar levels 4..6 (pool L3 output in fB) ----
    const float* cur = fB;
    for (int L = 4; L < 7; L++) {
        const int* np = pn + L;
        k_pairs<<<ceildiv(NB[L], 256), 256>>>(linCur, gridCur, np, S[L]);
        int ci1 = Cin1[L], co1 = Cout1[L];
        float* o1 = (cur == fB) ? fA : fB;
        {
            k_fill<<<ceildiv(NB[L] * co1, 256), 256>>>((int*)o1, 0, NB[L] * co1);
            dim3 g(ceildiv(NB[L], 16), co1 / 32, 27);
            k_conv_small2<<<g, 256>>>(cur, w[2 * L], o1, np, ci1, co1);
        }
        float* o2 = (L == 6) ? (float*)d_out : ((o1 == fA) ? fB : fA);
        {
            int zn = (L == 6) ? out_size : NB[L] * co1;
            k_fill<<<ceildiv(zn, 256), 256>>>((int*)o2, 0, zn);
            dim3 g(ceildiv(NB[L], 16), co1 / 32, 27);
            k_conv_small2<<<g, 256>>>(o1, w[2 * L + 1], o2, np, co1, co1);
        }
        cur = o2;
        if (L < 6) {
            int Sc = S[L] >> 1, P = Sc * Sc * Sc, nb = ceildiv(P, 1024);
            k_flags<<<ceildiv(P, 256), 256>>>(gridCur, S[L]);
            k_scanA<<<nb, 256>>>(P);
            k_scanB<<<1, 256>>>(nb, L + 1);
            k_scanC<<<nb, 256>>>(gridNxt, linNxt, P);
            float* po = (cur == fA) ? fB : fA;
            k_pool2<<<NB[L + 1], co1>>>(cur, po, nullptr, gridCur, linNxt,
                                        pn + L + 1, S[L], co1, 0);
            cur = po;
            int* t;
            t = linCur; linCur = linNxt; linNxt = t;
            t = gridCur; gridCur = gridNxt; gridNxt = t;
        }
    }
}

// round 17
// speedup vs baseline: 1.9133x; 1.0133x over previous
#include <cuda_runtime.h>
#include <cuda_fp16.h>
#include <cstdint>

// ---------------------------------------------------------------------------
// Sparse submanifold 3D conv backbone, batch=1, 128^3 -> 2^3.
// L0 conv1 (Cin=3): neighbor-skipping scalar, writes fp16 feature table.
// L0c2..L3: mma.sync pure fp16 (fp32 accum), 3-buffer pipeline with ONE
// __syncthreads per stage. HALF template skips the zero upper half of the
// last K-chunk for layers with Cin % 64 == 32 (exact).
// Levels 4-6 (n <= 512): k-split scalar conv (grid.z=27) + atomicAdd.
// ---------------------------------------------------------------------------

#define NMAX 100000
#define GRID_CELLS (1 << 21)
#define FLAGS_MAX (1 << 18)

__device__ int   g_n[8];
__device__ int   g_linA[NMAX];
__device__ int   g_linB[NMAX];
__device__ int   g_gridA[GRID_CELLS];
__device__ int   g_gridB[GRID_CELLS];
__device__ int   g_pairs[27 * NMAX];
__device__ int   g_flags[FLAGS_MAX];
__device__ int   g_bsums[256];
__device__ __align__(1024) float g_featA[10000000];
__device__ __align__(1024) float g_featB[10000000];
// fp16 feature tables: t1 = conv1 input, t2 = conv2 input
__device__ __align__(1024) __half g_fh1[12000000];
__device__ __align__(1024) __half g_fh2[12000000];
// pre-swizzled, transposed fp16 weight blob (layers 1..7)
__device__ __align__(1024) unsigned char g_wblob[16 * 1024 * 1024];

// ---------------------------------------------------------------------------

__device__ __forceinline__ void cp_async16(uint32_t dst, const void* src, int srcBytes) {
    asm volatile("cp.async.cg.shared.global [%0], [%1], 16, %2;\n"
                 :: "r"(dst), "l"(src), "r"(srcBytes));
}
__device__ __forceinline__ void cp_commit() {
    asm volatile("cp.async.commit_group;\n");
}
__device__ __forceinline__ uint32_t smem_u32(const void* p) {
    uint32_t a;
    asm("{ .reg .u64 t; cvta.to.shared.u64 t, %1; cvt.u32.u64 %0, t; }" : "=r"(a) : "l"(p));
    return a;
}
__device__ __forceinline__ void ldsm4(uint32_t* r, uint32_t addr) {
    asm volatile("ldmatrix.sync.aligned.m8n8.x4.shared.b16 {%0,%1,%2,%3}, [%4];"
                 : "=r"(r[0]), "=r"(r[1]), "=r"(r[2]), "=r"(r[3]) : "r"(addr));
}
__device__ __forceinline__ void ldsm2(uint32_t* r, uint32_t addr) {
    asm volatile("ldmatrix.sync.aligned.m8n8.x2.shared.b16 {%0,%1}, [%2];"
                 : "=r"(r[0]), "=r"(r[1]) : "r"(addr));
}
__device__ __forceinline__ void mma16816(float* d, const uint32_t* a, const uint32_t* b) {
    asm volatile("mma.sync.aligned.m16n8k16.row.col.f32.f16.f16.f32 "
                 "{%0,%1,%2,%3}, {%4,%5,%6,%7}, {%8,%9}, {%0,%1,%2,%3};"
                 : "+f"(d[0]), "+f"(d[1]), "+f"(d[2]), "+f"(d[3])
                 : "r"(a[0]), "r"(a[1]), "r"(a[2]), "r"(a[3]), "r"(b[0]), "r"(b[1]));
}

// ---------------------------------------------------------------------------

__global__ void k_setn(int n0) { g_n[0] = n0; }

__global__ void k_fill(int* g, int v, int P) {
    int i = blockIdx.x * blockDim.x + threadIdx.x;
    if (i < P) g[i] = v;
}

__global__ void k_scatter0(const int* __restrict__ coors, int n0) {
    int i = blockIdx.x * blockDim.x + threadIdx.x;
    if (i >= n0) return;
    int z = coors[i * 4 + 1];
    int y = coors[i * 4 + 2];
    int x = coors[i * 4 + 3];
    int l = (z * 128 + y) * 128 + x;
    g_linA[i] = l;
    g_gridA[l] = i;
}

__global__ void k_pairs(const int* __restrict__ lin, const int* __restrict__ grid,
                        const int* __restrict__ np, int S) {
    int n = *np;
    int i = blockIdx.x * blockDim.x + threadIdx.x;
    if (i >= n) return;
    int l = lin[i];
    int z = l / (S * S);
    int rem = l - z * S * S;
    int y = rem / S;
    int x = rem - y * S;
    int k = 0;
    #pragma unroll
    for (int dz = -1; dz <= 1; dz++)
        #pragma unroll
        for (int dy = -1; dy <= 1; dy++)
            #pragma unroll
            for (int dx = -1; dx <= 1; dx++) {
                int zz = z + dz, yy = y + dy, xx = x + dx;
                int v = -1;
                if (zz >= 0 && zz < S && yy >= 0 && yy < S && xx >= 0 && xx < S)
                    v = grid[(zz * S + yy) * S + xx];
                g_pairs[k * NMAX + i] = v;
                k++;
            }
}

// Weight blob: W[27,Cin,Cout] fp32 -> per-chunk SW128 images of W^T
// [Cout rows x 64 cols] fp16. Chunk = (k, ci-chunk).
__global__ void k_wcvt(const float* __restrict__ W, unsigned char* __restrict__ blob,
                       int Cin, int CinP, int Cout) {
    int total = 27 * CinP * Cout;
    int idx = blockIdx.x * 256 + threadIdx.x;
    if (idx >= total) return;
    int ci = idx % CinP;
    int t = idx / CinP;
    int co = t % Cout;
    int k = t / Cout;
    float v = (ci < Cin) ? W[((size_t)k * Cin + ci) * Cout + co] : 0.f;
    __half h = __float2half_rn(v);
    int ch = ci >> 6, cic = ci & 63;
    int sw = (((cic >> 3) ^ (co & 7)) << 4) + (cic & 7) * 2;
    int NCH = CinP >> 6;
    size_t stageBase = (size_t)(k * NCH + ch) * (Cout * 128);
    *(__half*)(blob + stageBase + (size_t)co * 128 + sw) = h;
}

// ---------------------------------------------------------------------------
// Fused L0 conv1: Cin=3, Cout=64, writes fp16 table (CP=64), skips missing.
// ---------------------------------------------------------------------------
__global__ __launch_bounds__(256) void k_conv0(const float* __restrict__ feats,
                                               const float* __restrict__ W,
                                               __half* __restrict__ out,
                                               const int* __restrict__ np) {
    __shared__ float Ws[27 * 3 * 64];
    int n = *np;
    int tid = threadIdx.x;
    for (int e = tid; e < 27 * 3 * 64; e += 256) Ws[e] = W[e];
    __syncthreads();
    int r = blockIdx.x * 4 + (tid >> 6);
    int lane = tid & 63;
    if (r >= n) return;
    float acc = 0.f;
    #pragma unroll 1
    for (int k = 0; k < 27; k++) {
        int id = g_pairs[k * NMAX + r];
        if (id >= 0) {
            float f0 = feats[id * 3 + 0];
            float f1 = feats[id * 3 + 1];
            float f2 = feats[id * 3 + 2];
            const float* wk = Ws + k * 192;
            acc += f0 * wk[lane] + f1 * wk[64 + lane] + f2 * wk[128 + lane];
        }
    }
    out[(size_t)r * 64 + lane] = __float2half_rn(acc);
}

// ---------------------------------------------------------------------------
// mma.sync conv: 128-row tile x CoutS col slice, pure fp16, fp32 accumulate.
// 512 threads = 16 warps = 4 row-groups x 4 col-quarters.
// 3-buffer cp.async pipeline, ONE __syncthreads per stage:
//   iter s: wait(stage s) -> sync -> issue load(stage s+2 into (s+2)%3)
//           -> compute buffer s%3.
// Buffer (s+2)%3 was last read at iter s-1, protected by the top sync.
// HALF: skip chunks 2-3 (zero cols) of the last ci-chunk of each k.
// ---------------------------------------------------------------------------
template <int NT, bool HALF>   // NT = CoutS/8
__global__ __launch_bounds__(512) void k_wconv(
    const __half* __restrict__ fin,
    const unsigned char* __restrict__ wblob,
    float* __restrict__ outF,
    __half* __restrict__ outH, int CP,
    const int* __restrict__ np, int CinP, int CoutF)
{
    const int NT4 = NT / 4;
    const int CoutS = NT * 8;
    const int WstageS = CoutS * 128;
    int n = *np;
    int rowBase = blockIdx.x * 128;
    if (rowBase >= n) return;
    int colBase = blockIdx.y * CoutS;

    extern __shared__ __align__(1024) unsigned char sm[];
    const uint32_t Asm = smem_u32(sm);        // 3 stages x 16KB
    const uint32_t Wsm = Asm + 3 * 16384;     // 3 stages x WstageS

    int tid = threadIdx.x;
    int wid = tid >> 5;
    int lane = tid & 31;

    const int NCH = CinP >> 6;
    const int S = 27 * NCH;
    const int WstageF = CoutF * 128;

    // A-gather: 4 threads per row, each loads 2 x 16B chunks
    int am = tid >> 2;        // 0..127 row
    int q = tid & 3;          // chunk group
    int r_g = rowBase + am;
    int curK = -1, curId = -1;

    float acc[2][NT4][4];
    #pragma unroll
    for (int mt = 0; mt < 2; mt++)
        #pragma unroll
        for (int j = 0; j < NT4; j++)
            #pragma unroll
            for (int p = 0; p < 4; p++) acc[mt][j][p] = 0.f;

    auto load = [&](int buf, int s) {
        int k = s / NCH;
        int ch = s - k * NCH;
        if (k != curK) {
            curK = k;
            curId = (r_g < n) ? g_pairs[k * NMAX + r_g] : -1;
        }
        {
            const unsigned char* src =
                (const unsigned char*)(fin + (size_t)(curId < 0 ? 0 : curId) * CinP + ch * 64);
            uint32_t dst = Asm + buf * 16384 + am * 128;
            int m7 = (am & 7) << 4;
            int sz = (curId >= 0) ? 16 : 0;
            #pragma unroll
            for (int c = q * 2; c < q * 2 + 2; c++)
                cp_async16(dst + ((c << 4) ^ m7), src + c * 16, sz);
        }
        {
            const unsigned char* src = wblob + (size_t)s * WstageF
                                     + (size_t)colBase * 128;
            const int hc = (CoutS * 128) >> 4;
            uint32_t dst = Wsm + buf * WstageS;
            for (int e = tid; e < hc; e += 512)
                cp_async16(dst + e * 16, src + e * 16, 16);
        }
        cp_commit();
    };

    int rw = wid & 3;
    int cw = wid >> 2;
    int arow0 = rw * 32 + (lane & 15);
    int ac16 = (lane >> 4) & 1;
    int brow_l = lane & 7;
    int bc16 = (lane >> 3) & 1;

    // prologue: stages 0 and 1 in flight
    load(0, 0);
    if (S > 1) load(1, 1);

    for (int s = 0; s < S; s++) {
        int b = s % 3;
        if (s + 1 < S) {
            asm volatile("cp.async.wait_group 1;\n");   // stage s complete
        } else {
            asm volatile("cp.async.wait_group 0;\n");
        }
        __syncthreads();                                // s-1 compute done everywhere
        if (s + 2 < S)
            load((s + 2) % 3, s + 2);                   // overwrites buffer read at s-1

        uint32_t AhB = Asm + b * 16384;
        uint32_t WhB = Wsm + b * WstageS;
        bool full = true;
        if (HALF) {
            int k2 = s / NCH;
            full = (s - k2 * NCH) != (NCH - 1);
        }

        #pragma unroll
        for (int chunk = 0; chunk < 4; chunk++) {
            if (chunk < 2 || full) {
                uint32_t ah[2][4];
                #pragma unroll
                for (int mt = 0; mt < 2; mt++) {
                    uint32_t off = (uint32_t)(arow0 + mt * 16) * 128 + chunk * 32 + ac16 * 16;
                    off ^= (off >> 3) & 0x70;
                    ldsm4(ah[mt], AhB + off);
                }
                #pragma unroll
                for (int j = 0; j < NT4; j++) {
                    uint32_t off = (uint32_t)(cw * (NT4 * 8) + j * 8 + brow_l) * 128
                                 + chunk * 32 + bc16 * 16;
                    off ^= (off >> 3) & 0x70;
                    uint32_t bh[2];
                    ldsm2(bh, WhB + off);
                    #pragma unroll
                    for (int mt = 0; mt < 2; mt++)
                        mma16816(acc[mt][j], ah[mt], bh);
                }
            }
        }
    }

    __syncthreads();   // last stage compute done before epilogue smem-free exit

    int grp = lane >> 2, tg = lane & 3;
    #pragma unroll
    for (int mt = 0; mt < 2; mt++) {
        int r0 = rowBase + rw * 32 + mt * 16 + grp;
        #pragma unroll
        for (int half = 0; half < 2; half++) {
            int r = r0 + half * 8;
            if (r >= n) continue;
            #pragma unroll
            for (int j = 0; j < NT4; j++) {
                float d0 = acc[mt][j][half * 2 + 0];
                float d1 = acc[mt][j][half * 2 + 1];
                int c = colBase + cw * (NT4 * 8) + j * 8 + tg * 2;
                if (outF) {
                    float2 v; v.x = d0; v.y = d1;
                    *(float2*)(outF + (size_t)r * CoutF + c) = v;
                }
                if (outH) {
                    __half h0 = __float2half_rn(d0);
                    __half h1 = __float2half_rn(d1);
                    uint32_t hp = ((uint32_t)(*(unsigned short*)&h1) << 16)
                                | (uint32_t)(*(unsigned short*)&h0);
                    *(uint32_t*)(outH + (size_t)r * CP + c) = hp;
                }
            }
            if (outH && blockIdx.y == 0 && cw == 0) {
                for (int c = CoutF + tg * 2; c < CP; c += 8)
                    *(uint32_t*)(outH + (size_t)r * CP + c) = 0u;
            }
        }
    }
}

// ---------------------------------------------------------------------------
// Small-level conv, k-split: grid (rows/16, Cout/32, 27). Each block handles
// one kernel offset; partials atomicAdd'ed into zero-initialized out.
// ---------------------------------------------------------------------------
__global__ __launch_bounds__(256) void k_conv_small2(const float* __restrict__ feats,
                                                     const float* __restrict__ W,
                                                     float* __restrict__ out,
                                                     const int* __restrict__ np,
                                                     int Cin, int Cout) {
    int n = *np;
    int rowBase = blockIdx.x * 16;
    if (rowBase >= n) return;
    int colBase = blockIdx.y * 32;
    int k = blockIdx.z;

    __shared__ float As[16][33];
    __shared__ float Ws[32][33];
    __shared__ int sIdx[16];

    int tid = threadIdx.x;
    int tm = tid >> 5;
    int tn = tid & 31;

    if (tid < 16) {
        int r = rowBase + tid;
        sIdx[tid] = (r < n) ? g_pairs[k * NMAX + r] : -1;
    }

    float acc0 = 0.f, acc1 = 0.f;

    for (int c0 = 0; c0 < Cin; c0 += 32) {
        __syncthreads();
        {
            int e = tid;
            #pragma unroll
            for (int j = 0; j < 2; j++, e += 256) {
                int m = e >> 5, c = e & 31;
                int id = sIdx[m];
                As[m][c] = (id >= 0) ? feats[(size_t)id * Cin + c0 + c] : 0.f;
            }
        }
        {
            const float* Wk = W + ((size_t)k * Cin + c0) * Cout + colBase;
            int e = tid;
            #pragma unroll
            for (int j = 0; j < 4; j++, e += 256) {
                int kk = e >> 5, c = e & 31;
                Ws[kk][c] = Wk[(size_t)kk * Cout + c];
            }
        }
        __syncthreads();
        #pragma unroll 8
        for (int kk = 0; kk < 32; kk++) {
            float w = Ws[kk][tn];
            acc0 += As[tm * 2][kk] * w;
            acc1 += As[tm * 2 + 1][kk] * w;
        }
    }

    int r0 = rowBase + tm * 2;
    if (r0 < n)     atomicAdd(&out[(size_t)r0 * Cout + colBase + tn], acc0);
    if (r0 + 1 < n) atomicAdd(&out[(size_t)(r0 + 1) * Cout + colBase + tn], acc1);
}

// ---------------------------------------------------------------------------
// Pool structure kernels + pool with optional fp16 output table
// ---------------------------------------------------------------------------
__global__ void k_flags(const int* __restrict__ fineGrid, int S) {
    int Sc = S >> 1;
    int P = Sc * Sc * Sc;
    int p = blockIdx.x * blockDim.x + threadIdx.x;
    if (p >= P) return;
    int pz = p / (Sc * Sc);
    int rem = p - pz * Sc * Sc;
    int py = rem / Sc;
    int px = rem - py * Sc;
    int occ = 0;
    #pragma unroll
    for (int a = 0; a < 2; a++)
        #pragma unroll
        for (int b = 0; b < 2; b++)
            #pragma unroll
            for (int c = 0; c < 2; c++) {
                int l = ((2 * pz + a) * S + 2 * py + b) * S + 2 * px + c;
                if (fineGrid[l] >= 0) occ = 1;
            }
    g_flags[p] = occ;
}

__global__ void k_scanA(int P) {
    __shared__ int sh[256];
    int t = threadIdx.x;
    int base = blockIdx.x * 1024;
    int s = 0;
    #pragma unroll
    for (int j = 0; j < 4; j++) {
        int p = base + t * 4 + j;
        if (p < P) s += g_flags[p];
    }
    sh[t] = s;
    __syncthreads();
    for (int d = 128; d > 0; d >>= 1) {
        if (t < d) sh[t] += sh[t + d];
        __syncthreads();
    }
    if (t == 0) g_bsums[blockIdx.x] = sh[0];
}

__global__ void k_scanB(int nb, int Lnext) {
    __shared__ int sh[256];
    int t = threadIdx.x;
    int v = (t < nb) ? g_bsums[t] : 0;
    sh[t] = v;
    __syncthreads();
    for (int d = 1; d < 256; d <<= 1) {
        int x = (t >= d) ? sh[t - d] : 0;
        __syncthreads();
        sh[t] += x;
        __syncthreads();
    }
    if (t < nb) g_bsums[t] = sh[t] - v;
    if (t == 255) g_n[Lnext] = sh[255];
}

__global__ void k_scanC(int* __restrict__ coarseGrid, int* __restrict__ linNext, int P) {
    __shared__ int sh[256];
    int t = threadIdx.x;
    int base = blockIdx.x * 1024;
    int f[4];
    int s = 0;
    #pragma unroll
    for (int j = 0; j < 4; j++) {
        int p = base + t * 4 + j;
        f[j] = (p < P) ? g_flags[p] : 0;
        s += f[j];
    }
    int v = s;
    sh[t] = v;
    __syncthreads();
    for (int d = 1; d < 256; d <<= 1) {
        int x = (t >= d) ? sh[t - d] : 0;
        __syncthreads();
        sh[t] += x;
        __syncthreads();
    }
    int off = g_bsums[blockIdx.x] + sh[t] - v;
    #pragma unroll
    for (int j = 0; j < 4; j++) {
        int p = base + t * 4 + j;
        if (p >= P) break;
        if (f[j]) {
            coarseGrid[p] = off;
            linNext[off] = p;
            off++;
        } else {
            coarseGrid[p] = -1;
        }
    }
}

__global__ void k_pool2(const float* __restrict__ feats, float* __restrict__ out,
                        __half* __restrict__ oh,
                        const int* __restrict__ fineGrid, const int* __restrict__ linNext,
                        const int* __restrict__ np, int S, int C, int CP) {
    int row = blockIdx.x;
    if (row >= *np) return;
    int Sc = S >> 1;
    int p = linNext[row];
    int pz = p / (Sc * Sc);
    int rem = p - pz * Sc * Sc;
    int py = rem / Sc;
    int px = rem - py * Sc;
    int c = threadIdx.x;
    if (c < C) {
        float m = -3.4e38f;
        #pragma unroll
        for (int a = 0; a < 2; a++)
            #pragma unroll
            for (int b = 0; b < 2; b++)
                #pragma unroll
                for (int d = 0; d < 2; d++) {
                    int l = ((2 * pz + a) * S + 2 * py + b) * S + 2 * px + d;
                    int r = fineGrid[l];
                    if (r >= 0) m = fmaxf(m, feats[(size_t)r * C + c]);
                }
        out[(size_t)row * C + c] = m;
        if (CP) oh[(size_t)row * CP + c] = __float2half_rn(m);
    } else if (CP && c < CP) {
        oh[(size_t)row * CP + c] = __float2half_rn(0.f);
    }
}

// ---------------------------------------------------------------------------

static inline int ceildiv(int a, int b) { return (a + b - 1) / b; }
static inline int pad64(int c) { return (c + 63) & ~63; }

static void launch_wconv(const __half* fin, const unsigned char* wb, float* outF,
                         __half* oh, int CP, const int* np, int CinP, int Cout,
                         int nBound, int gy, bool half) {
    int CoutS = Cout / gy;
    int NT = CoutS / 8;
    dim3 g(ceildiv(nBound, 128), gy), b(512);
    int smem = 3 * 16384 + 3 * CoutS * 128;
#define LW_CASE(NTV)                                                                     \
    if (half) {                                                                          \
        cudaFuncSetAttribute(k_wconv<NTV, true>,                                         \
                             cudaFuncAttributeMaxDynamicSharedMemorySize, smem);         \
        k_wconv<NTV, true><<<g, b, smem>>>(fin, wb, outF, oh, CP, np, CinP, Cout);       \
    } else {                                                                             \
        cudaFuncSetAttribute(k_wconv<NTV, false>,                                        \
                             cudaFuncAttributeMaxDynamicSharedMemorySize, smem);         \
        k_wconv<NTV, false><<<g, b, smem>>>(fin, wb, outF, oh, CP, np, CinP, Cout);      \
    }
    switch (NT) {
        case 4:  LW_CASE(4)  break;
        case 8:  LW_CASE(8)  break;
        case 12: LW_CASE(12) break;
        case 16: LW_CASE(16) break;
    }
#undef LW_CASE
}

extern "C" void kernel_launch(void* const* d_in, const int* in_sizes, int n_in,
                              void* d_out, int out_size) {
    const float* feat_in = (const float*)d_in[0];
    const int*   coors   = (const int*)d_in[1];
    const float* w[14];
    for (int i = 0; i < 14; i++) w[i] = (const float*)d_in[3 + i];

    int n0 = in_sizes[0] / 3;

    float *fA, *fB;
    __half *t1, *t2;
    unsigned char* wblob;
    int *gA, *gB, *lA, *lB, *pn;
    cudaGetSymbolAddress((void**)&fA, g_featA);
    cudaGetSymbolAddress((void**)&fB, g_featB);
    cudaGetSymbolAddress((void**)&t1, g_fh1);
    cudaGetSymbolAddress((void**)&t2, g_fh2);
    cudaGetSymbolAddress((void**)&wblob, g_wblob);
    cudaGetSymbolAddress((void**)&gA, g_gridA);
    cudaGetSymbolAddress((void**)&gB, g_gridB);
    cudaGetSymbolAddress((void**)&lA, g_linA);
    cudaGetSymbolAddress((void**)&lB, g_linB);
    cudaGetSymbolAddress((void**)&pn, g_n);

    const int S[7]  = {128, 64, 32, 16, 8, 4, 2};
    int NB[7];
    NB[0] = n0;
    NB[1] = n0 < (64 * 64 * 64) ? n0 : (64 * 64 * 64);
    NB[2] = 32 * 32 * 32;
    NB[3] = 16 * 16 * 16;
    NB[4] = 8 * 8 * 8;
    NB[5] = 4 * 4 * 4;
    NB[6] = 2 * 2 * 2;
    const int Cin1[7]  = {3, 64, 96, 128, 160, 192, 224};
    const int Cout1[7] = {64, 96, 128, 160, 192, 224, 256};

    // MMA-path layers (0..7 == L0c1..L3c2); layer 0 handled by k_conv0
    const int LCin[8]  = {3, 64, 64, 96, 96, 128, 128, 160};
    const int LCinP[8] = {64, 64, 64, 128, 128, 128, 128, 192};
    const int LCout[8] = {64, 64, 96, 96, 128, 128, 160, 160};
    size_t woff[9];
    woff[0] = 0;
    for (int i = 0; i < 8; i++)
        woff[i + 1] = woff[i] + (size_t)27 * (LCinP[i] / 64) * LCout[i] * 128;

    // ---- weight blob (layers 1..7) + level-0 structure ----
    for (int i = 1; i < 8; i++) {
        int total = 27 * LCinP[i] * LCout[i];
        k_wcvt<<<ceildiv(total, 256), 256>>>(w[i], wblob + woff[i],
                                             LCin[i], LCinP[i], LCout[i]);
    }
    k_setn<<<1, 1>>>(n0);
    k_fill<<<ceildiv(GRID_CELLS, 256), 256>>>(gA, -1, GRID_CELLS);
    k_scatter0<<<ceildiv(n0, 256), 256>>>(coors, n0);

    int* linCur = lA;
    int* gridCur = gA;
    int* linNxt = lB;
    int* gridNxt = gB;

    // ---- MMA levels 0..3 ----
    for (int L = 0; L < 4; L++) {
        const int* np = pn + L;
        k_pairs<<<ceildiv(NB[L], 256), 256>>>(linCur, gridCur, np, S[L]);

        int li1 = 2 * L, li2 = 2 * L + 1;
        int gy = (L == 3) ? 5 : 1;
        if (L == 0) {
            k_conv0<<<ceildiv(NB[0], 4), 256>>>(feat_in, w[0], t2, np);
        } else {
            launch_wconv(t1, wblob + woff[li1], nullptr, t2, LCinP[li2],
                         np, LCinP[li1], LCout[li1], NB[L], gy,
                         (LCin[li1] & 63) == 32);
        }
        launch_wconv(t2, wblob + woff[li2], fA, nullptr, 0,
                     np, LCinP[li2], LCout[li2], NB[L], gy,
                     (LCin[li2] & 63) == 32);

        {
            int Sc = S[L] >> 1, P = Sc * Sc * Sc, nb = ceildiv(P, 1024);
            k_flags<<<ceildiv(P, 256), 256>>>(gridCur, S[L]);
            k_scanA<<<nb, 256>>>(P);
            k_scanB<<<1, 256>>>(nb, L + 1);
            k_scanC<<<nb, 256>>>(gridNxt, linNxt, P);
            int C = LCout[li2];
            int CP = (L < 3) ? pad64(C) : 0;
            int thr = CP ? CP : C;
            k_pool2<<<NB[L + 1], thr>>>(fA, fB, t1, gridCur, linNxt,
                                        pn + L + 1, S[L], C, CP);
        }
        int* t;
        t = linCur; linCur = linNxt; linNxt = t;
        t = gridCur; gridCur = gridNxt; gridNxt = t;
    }

    // ---- k-split scalar levels 4..6 (pool L3 output in fB) ----
    const float* cur = fB;
    for (int L = 4; L < 7; L++) {
        const int* np = pn + L;
        k_pairs<<<ceildiv(NB[L], 256), 256>>>(linCur, gridCur, np, S[L]);
        int ci1 = Cin1[L], co1 = Cout1[L];
        float* o1 = (cur == fB) ? fA : fB;
        {
            k_fill<<<ceildiv(NB[L] * co1, 256), 256>>>((int*)o1, 0, NB[L] * co1);
            dim3 g(ceildiv(NB[L], 16), co1 / 32, 27);
            k_conv_small2<<<g, 256>>>(cur, w[2 * L], o1, np, ci1, co1);
        }
        float* o2 = (L == 6) ? (float*)d_out : ((o1 == fA) ? fB : fA);
        {
            int zn = (L == 6) ? out_size : NB[L] * co1;
            k_fill<<<ceildiv(zn, 256), 256>>>((int*)o2, 0, zn);
            dim3 g(ceildiv(NB[L], 16), co1 / 32, 27);
            k_conv_small2<<<g, 256>>>(o1, w[2 * L + 1], o2, np, co1, co1);
        }
        cur = o2;
        if (L < 6) {
            int Sc = S[L] >> 1, P = Sc * Sc * Sc, nb = ceildiv(P, 1024);
            k_flags<<<ceildiv(P, 256), 256>>>(gridCur, S[L]);
            k_scanA<<<nb, 256>>>(P);
            k_scanB<<<1, 256>>>(nb, L + 1);
            k_scanC<<<nb, 256>>>(gridNxt, linNxt, P);
            float* po = (cur == fA) ? fB : fA;
            k_pool2<<<NB[L + 1], co1>>>(cur, po, nullptr, gridCur, linNxt,
                                        pn + L + 1, S[L], co1, 0);
            cur = po;
            int* t;
            t = linCur; linCur = linNxt; linNxt = t;
            t = gridCur; gridCur = gridNxt; gridNxt = t;
        }
    }
}